// round 11
// baseline (speedup 1.0000x reference)
#include <cuda_runtime.h>
#include <cuda_bf16.h>
#include <stdint.h>
#include <math.h>

#define H 1024
#define F 4096
#define E 8
#define TK 2
#define T 8192

#define BM 128
#define BN1 64            // gemm1 N tile
#define BN2 128           // gemm2 N tile
#define BK 32
#define NSTAGE 3
#define NT 512            // threads per CTA

#define APITCH 40
#define B1PITCH 72
#define B2PITCH 136
#define A_BYTES  (BM * APITCH * 2)      // 10240
#define B1_BYTES (BK * B1PITCH * 2)     // 4608
#define B2_BYTES (BK * B2PITCH * 2)     // 8704
#define STAGE1  (2 * A_BYTES + 4 * B1_BYTES)   // 38912
#define STAGE2  (2 * A_BYTES + 2 * B2_BYTES)   // 37888
#define SMEM1   (NSTAGE * STAGE1 + 512)
#define SMEM2   (NSTAGE * STAGE2)

// ---- device scratch ----
__device__ int   g_cnt[E];
__device__ int   g_idx[E][T];
__device__ float g_cw[E][T];
__device__ float g_sumprob[E];
__device__ float g_zsum;

__device__ __align__(16) __nv_bfloat16 g_xh[(size_t)T * H];
__device__ __align__(16) __nv_bfloat16 g_xl[(size_t)T * H];
__device__ __align__(16) __nv_bfloat16 g_wgh[(size_t)E * H * F];
__device__ __align__(16) __nv_bfloat16 g_wgl[(size_t)E * H * F];
__device__ __align__(16) __nv_bfloat16 g_wuh[(size_t)E * H * F];
__device__ __align__(16) __nv_bfloat16 g_wul[(size_t)E * H * F];
__device__ __align__(16) __nv_bfloat16 g_wdh[(size_t)E * F * H];
__device__ __align__(16) __nv_bfloat16 g_wdl[(size_t)E * F * H];
// expert e owns rows [e*T, e*T+cnt[e])
__device__ __align__(16) __nv_bfloat16 g_hh[(size_t)E * T * F];
__device__ __align__(16) __nv_bfloat16 g_hl[(size_t)E * T * F];

// ---------------------------------------------------------------------------
__device__ __forceinline__ unsigned sptr(const void* p) {
    return (unsigned)__cvta_generic_to_shared(p);
}
__device__ __forceinline__ void ldsm4(unsigned* r, unsigned a) {
    asm volatile("ldmatrix.sync.aligned.m8n8.x4.shared.b16 {%0,%1,%2,%3}, [%4];"
                 : "=r"(r[0]), "=r"(r[1]), "=r"(r[2]), "=r"(r[3]) : "r"(a));
}
__device__ __forceinline__ void ldsm4t(unsigned* r, unsigned a) {
    asm volatile("ldmatrix.sync.aligned.m8n8.x4.trans.shared.b16 {%0,%1,%2,%3}, [%4];"
                 : "=r"(r[0]), "=r"(r[1]), "=r"(r[2]), "=r"(r[3]) : "r"(a));
}
__device__ __forceinline__ void mma16816(float* d, const unsigned* a, const unsigned* b) {
    asm volatile("mma.sync.aligned.m16n8k16.row.col.f32.bf16.bf16.f32 "
                 "{%0,%1,%2,%3},{%4,%5,%6,%7},{%8,%9},{%0,%1,%2,%3};"
                 : "+f"(d[0]), "+f"(d[1]), "+f"(d[2]), "+f"(d[3])
                 : "r"(a[0]), "r"(a[1]), "r"(a[2]), "r"(a[3]), "r"(b[0]), "r"(b[1]));
}
__device__ __forceinline__ void split2(float x, float y, unsigned& hi, unsigned& lo) {
    __nv_bfloat16 hx = __float2bfloat16(x);
    __nv_bfloat16 hy = __float2bfloat16(y);
    __nv_bfloat16 lx = __float2bfloat16(x - __bfloat162float(hx));
    __nv_bfloat16 ly = __float2bfloat16(y - __bfloat162float(hy));
    __nv_bfloat162 h = __halves2bfloat162(hx, hy);
    __nv_bfloat162 l = __halves2bfloat162(lx, ly);
    hi = *reinterpret_cast<unsigned*>(&h);
    lo = *reinterpret_cast<unsigned*>(&l);
}
__device__ __forceinline__ void cpasync16(unsigned dst, const void* src, int sz) {
    asm volatile("cp.async.cg.shared.global [%0], [%1], 16, %2;\n"
                 :: "r"(dst), "l"(src), "r"(sz));
}
__device__ __forceinline__ void cpcommit() { asm volatile("cp.async.commit_group;\n"); }
__device__ __forceinline__ void cpwait1()  { asm volatile("cp.async.wait_group 1;\n"); }

// ---------------------------------------------------------------------------
__global__ void convert_kernel(const float4* __restrict__ src, size_t n4, int which) {
    uint2* dh; uint2* dl;
    if (which == 0)      { dh = (uint2*)g_wgh; dl = (uint2*)g_wgl; }
    else if (which == 1) { dh = (uint2*)g_wuh; dl = (uint2*)g_wul; }
    else if (which == 2) { dh = (uint2*)g_wdh; dl = (uint2*)g_wdl; }
    else                 { dh = (uint2*)g_xh;  dl = (uint2*)g_xl;  }
    size_t stride = (size_t)gridDim.x * blockDim.x;
    for (size_t i = (size_t)blockIdx.x * blockDim.x + threadIdx.x; i < n4; i += stride) {
        float4 v = src[i];
        unsigned h0, l0, h1, l1;
        split2(v.x, v.y, h0, l0);
        split2(v.z, v.w, h1, l1);
        dh[i] = make_uint2(h0, h1);
        dl[i] = make_uint2(l0, l1);
    }
}

__global__ void zero_kernel(float* __restrict__ out) {
    size_t n = (size_t)T * H;
    size_t stride = (size_t)gridDim.x * blockDim.x;
    for (size_t i = (size_t)blockIdx.x * blockDim.x + threadIdx.x; i < n; i += stride)
        out[i] = 0.f;
    if (blockIdx.x == 0 && threadIdx.x < E) {
        g_cnt[threadIdx.x] = 0;
        g_sumprob[threadIdx.x] = 0.f;
    }
    if (blockIdx.x == 0 && threadIdx.x == E) g_zsum = 0.f;
}

__global__ void router_kernel(const float* __restrict__ x,
                              const float* __restrict__ gw) {
    int warp = threadIdx.x >> 5;
    int lane = threadIdx.x & 31;
    int t = blockIdx.x * (blockDim.x >> 5) + warp;
    if (t >= T) return;

    const float* xr = x + (size_t)t * H;
    float acc[E];
#pragma unroll
    for (int e = 0; e < E; e++) acc[e] = 0.f;
    for (int h = lane; h < H; h += 32) {
        float xv = xr[h];
#pragma unroll
        for (int e = 0; e < E; e++) acc[e] += xv * gw[h * E + e];
    }
#pragma unroll
    for (int off = 16; off; off >>= 1) {
#pragma unroll
        for (int e = 0; e < E; e++)
            acc[e] += __shfl_down_sync(0xffffffffu, acc[e], off);
    }
    if (lane == 0) {
        float m = acc[0];
#pragma unroll
        for (int e = 1; e < E; e++) m = fmaxf(m, acc[e]);
        float p[E], s = 0.f;
#pragma unroll
        for (int e = 0; e < E; e++) { p[e] = __expf(acc[e] - m); s += p[e]; }
        float inv = 1.f / s;
        float lse = m + logf(s);
        atomicAdd(&g_zsum, lse * lse);
        int i1 = 0; float p1 = -1.f;
#pragma unroll
        for (int e = 0; e < E; e++) {
            float pe = p[e] * inv;
            p[e] = pe;
            atomicAdd(&g_sumprob[e], pe);
            if (pe > p1) { p1 = pe; i1 = e; }
        }
        int i2 = -1; float p2 = -1.f;
#pragma unroll
        for (int e = 0; e < E; e++)
            if (e != i1 && p[e] > p2) { p2 = p[e]; i2 = e; }
        float rs = 1.f / (p1 + p2);
        int pos1 = atomicAdd(&g_cnt[i1], 1);
        g_idx[i1][pos1] = t; g_cw[i1][pos1] = p1 * rs;
        int pos2 = atomicAdd(&g_cnt[i2], 1);
        g_idx[i2][pos2] = t; g_cw[i2][pos2] = p2 * rs;
    }
}

// ---------------------------------------------------------------------------
// GEMM1 stage loader (512 threads): A gather hi/lo + 4 B tiles (gate/up hi/lo)
__device__ __forceinline__ void issue1(int k0, unsigned buf, const int* __restrict__ ridx,
                                       const __nv_bfloat16* __restrict__ wgh,
                                       const __nv_bfloat16* __restrict__ wgl,
                                       const __nv_bfloat16* __restrict__ wuh,
                                       const __nv_bfloat16* __restrict__ wul,
                                       int col0, int tid) {
    {   // A: 128 rows x 32 cols, one 16B chunk per thread (hi + lo)
        int r = tid >> 2, c = tid & 3;
        int tok = ridx[r];
        int sz = (tok >= 0) ? 16 : 0;
        size_t so = (size_t)(tok >= 0 ? tok : 0) * H + k0 + c * 8;
        unsigned da = buf + r * (APITCH * 2) + c * 16;
        cpasync16(da,           g_xh + so, sz);
        cpasync16(da + A_BYTES, g_xl + so, sz);
    }
    {   // B: threads 0-255 -> gate hi/lo, 256-511 -> up hi/lo
        int m2 = tid >> 8;
        int t2 = tid & 255;
        int br = t2 >> 3, bc = t2 & 7;
        size_t bo = (size_t)(k0 + br) * F + col0 + bc * 8;
        unsigned db = buf + 2 * A_BYTES + m2 * (2 * B1_BYTES) + br * (B1PITCH * 2) + bc * 16;
        const __nv_bfloat16* bh_ = m2 ? wuh : wgh;
        const __nv_bfloat16* bl_ = m2 ? wul : wgl;
        cpasync16(db,            bh_ + bo, 16);
        cpasync16(db + B1_BYTES, bl_ + bo, 16);
    }
}

// GEMM1: 128x64 tile, 16 warps (gate warps 0-7, up warps 8-15), bf16 hi/lo 3-pass.
__global__ __launch_bounds__(NT, 1) void gemm1_tc() {
    int e = blockIdx.z;
    int cnt = g_cnt[e];
    int row0 = blockIdx.y * BM;
    if (row0 >= cnt) return;
    int col0 = blockIdx.x * BN1;

    const __nv_bfloat16* wgh = g_wgh + (size_t)e * H * F;
    const __nv_bfloat16* wgl = g_wgl + (size_t)e * H * F;
    const __nv_bfloat16* wuh = g_wuh + (size_t)e * H * F;
    const __nv_bfloat16* wul = g_wul + (size_t)e * H * F;

    extern __shared__ char smem[];
    unsigned sbase = sptr(smem);
    int* ridx = (int*)(smem + NSTAGE * STAGE1);

    int tid = threadIdx.x;
    int lane = tid & 31, wid = tid >> 5;
    int mat = wid >> 3;            // 0 = gate, 1 = up
    int w8 = wid & 7;
    int wm = (w8 & 3) * 32, wn = (w8 >> 2) * 32;

    if (tid < BM) { int r = row0 + tid; ridx[tid] = (r < cnt) ? g_idx[e][r] : -1; }
    __syncthreads();

    float acc[2][4][4];
#pragma unroll
    for (int b = 0; b < 2; b++)
#pragma unroll
        for (int c = 0; c < 4; c++)
#pragma unroll
            for (int d = 0; d < 4; d++) acc[b][c][d] = 0.f;

    const int NK = H / BK;   // 32
#pragma unroll
    for (int s = 0; s < NSTAGE - 1; s++) {
        issue1(s * BK, sbase + s * STAGE1, ridx, wgh, wgl, wuh, wul, col0, tid);
        cpcommit();
    }
    cpwait1();
    __syncthreads();

    for (int kt = 0; kt < NK; kt++) {
        int kn = kt + NSTAGE - 1;
        if (kn < NK)
            issue1(kn * BK, sbase + (kn % NSTAGE) * STAGE1, ridx, wgh, wgl, wuh, wul, col0, tid);
        cpcommit();

        unsigned sb = sbase + (kt % NSTAGE) * STAGE1;
        unsigned bbase = sb + 2 * A_BYTES + mat * (2 * B1_BYTES);
#pragma unroll
        for (int ks = 0; ks < 2; ks++) {
            unsigned ah[2][4], al[2][4];
            int ar = wm + (lane & 15);
            int ac = ks * 16 + (lane >> 4) * 8;
#pragma unroll
            for (int mi = 0; mi < 2; mi++) {
                unsigned aoff = ((ar + mi * 16) * APITCH + ac) * 2;
                ldsm4(ah[mi], sb + aoff);
                ldsm4(al[mi], sb + A_BYTES + aoff);
            }
            int br = ks * 16 + (lane & 15), bc = wn + (lane >> 4) * 8;
            unsigned bh[2][4], bl[2][4];
#pragma unroll
            for (int nh = 0; nh < 2; nh++) {
                unsigned boff = (br * B1PITCH + bc + nh * 16) * 2;
                ldsm4t(bh[nh], bbase + boff);
                ldsm4t(bl[nh], bbase + B1_BYTES + boff);
            }
#pragma unroll
            for (int mi = 0; mi < 2; mi++)
#pragma unroll
                for (int nh = 0; nh < 2; nh++)
#pragma unroll
                    for (int s = 0; s < 2; s++) {
                        int nj = nh * 2 + s;
                        mma16816(acc[mi][nj], ah[mi], &bh[nh][s * 2]);
                        mma16816(acc[mi][nj], ah[mi], &bl[nh][s * 2]);
                        mma16816(acc[mi][nj], al[mi], &bh[nh][s * 2]);
                    }
        }
        cpwait1();
        __syncthreads();
    }

    // epilogue: gate warps stash acc in smem; up warps combine silu(g)*u
    float (*sg)[BN1 + 1] = (float(*)[BN1 + 1])smem;   // 128 x 65 floats, reuses stages
    if (mat == 0) {
#pragma unroll
        for (int mi = 0; mi < 2; mi++)
#pragma unroll
            for (int nj = 0; nj < 4; nj++)
#pragma unroll
                for (int k = 0; k < 4; k++) {
                    int m = wm + mi * 16 + (lane >> 2) + (k >> 1) * 8;
                    int n = wn + nj * 8 + (lane & 3) * 2 + (k & 1);
                    sg[m][n] = acc[mi][nj][k];
                }
    }
    __syncthreads();
    if (mat == 1) {
#pragma unroll
        for (int mi = 0; mi < 2; mi++)
#pragma unroll
            for (int half = 0; half < 2; half++) {
                int m = wm + mi * 16 + (lane >> 2) + half * 8;
                int r = row0 + m;
                if (r < cnt) {
                    size_t base = ((size_t)e * T + r) * F + col0 + wn + (lane & 3) * 2;
#pragma unroll
                    for (int nj = 0; nj < 4; nj++) {
                        int nl = wn + nj * 8 + (lane & 3) * 2;
                        float g0 = sg[m][nl];
                        float g1 = sg[m][nl + 1];
                        float u0 = acc[mi][nj][half * 2 + 0];
                        float u1 = acc[mi][nj][half * 2 + 1];
                        float h0 = g0 / (1.f + __expf(-g0)) * u0;
                        float h1 = g1 / (1.f + __expf(-g1)) * u1;
                        unsigned hh, hl;
                        split2(h0, h1, hh, hl);
                        *reinterpret_cast<unsigned*>(g_hh + base + nj * 8) = hh;
                        *reinterpret_cast<unsigned*>(g_hl + base + nj * 8) = hl;
                    }
                }
            }
    }
}

// ---------------------------------------------------------------------------
// GEMM2 stage loader (512 threads): A linear hi/lo + B (Wd) hi/lo 32x128
__device__ __forceinline__ void issue2(int k0, unsigned buf, size_t arow0, int rows,
                                       const __nv_bfloat16* __restrict__ wdh,
                                       const __nv_bfloat16* __restrict__ wdl,
                                       int col0, int tid) {
    {
        int r = tid >> 2, c = tid & 3;
        int sz = (r < rows) ? 16 : 0;
        size_t so = (arow0 + (r < rows ? r : 0)) * F + k0 + c * 8;
        unsigned da = buf + r * (APITCH * 2) + c * 16;
        cpasync16(da,           g_hh + so, sz);
        cpasync16(da + A_BYTES, g_hl + so, sz);
    }
    {
        int br = tid >> 4, bc = tid & 15;
        size_t bo = (size_t)(k0 + br) * H + col0 + bc * 8;
        unsigned db = buf + 2 * A_BYTES + br * (B2PITCH * 2) + bc * 16;
        cpasync16(db,            wdh + bo, 16);
        cpasync16(db + B2_BYTES, wdl + bo, 16);
    }
}

// GEMM2: 128x128 tile, 16 warps (4m x 4n), atomic scatter epilogue.
__global__ __launch_bounds__(NT, 1) void gemm2_tc(float* __restrict__ out) {
    int e = blockIdx.z;
    int cnt = g_cnt[e];
    int row0 = blockIdx.y * BM;
    if (row0 >= cnt) return;
    int col0 = blockIdx.x * BN2;
    int rows = cnt - row0; if (rows > BM) rows = BM;
    size_t arow0 = (size_t)e * T + row0;

    const __nv_bfloat16* wdh = g_wdh + (size_t)e * F * H;
    const __nv_bfloat16* wdl = g_wdl + (size_t)e * F * H;

    extern __shared__ char smem[];
    unsigned sbase = sptr(smem);

    int tid = threadIdx.x;
    int lane = tid & 31, wid = tid >> 5;
    int wm = (wid & 3) * 32, wn = (wid >> 2) * 32;

    float acc[2][4][4];
#pragma unroll
    for (int b = 0; b < 2; b++)
#pragma unroll
        for (int c = 0; c < 4; c++)
#pragma unroll
            for (int d = 0; d < 4; d++) acc[b][c][d] = 0.f;

    const int NK = F / BK;   // 128
#pragma unroll
    for (int s = 0; s < NSTAGE - 1; s++) {
        issue2(s * BK, sbase + s * STAGE2, arow0, rows, wdh, wdl, col0, tid);
        cpcommit();
    }
    cpwait1();
    __syncthreads();

    for (int kt = 0; kt < NK; kt++) {
        int kn = kt + NSTAGE - 1;
        if (kn < NK)
            issue2(kn * BK, sbase + (kn % NSTAGE) * STAGE2, arow0, rows, wdh, wdl, col0, tid);
        cpcommit();

        unsigned sb = sbase + (kt % NSTAGE) * STAGE2;
        unsigned bbase = sb + 2 * A_BYTES;
#pragma unroll
        for (int ks = 0; ks < 2; ks++) {
            unsigned ah[2][4], al[2][4];
            int ar = wm + (lane & 15);
            int ac = ks * 16 + (lane >> 4) * 8;
#pragma unroll
            for (int mi = 0; mi < 2; mi++) {
                unsigned aoff = ((ar + mi * 16) * APITCH + ac) * 2;
                ldsm4(ah[mi], sb + aoff);
                ldsm4(al[mi], sb + A_BYTES + aoff);
            }
            int br = ks * 16 + (lane & 15), bc = wn + (lane >> 4) * 8;
            unsigned bh[2][4], bl[2][4];
#pragma unroll
            for (int nh = 0; nh < 2; nh++) {
                unsigned boff = (br * B2PITCH + bc + nh * 16) * 2;
                ldsm4t(bh[nh], bbase + boff);
                ldsm4t(bl[nh], bbase + B2_BYTES + boff);
            }
#pragma unroll
            for (int mi = 0; mi < 2; mi++)
#pragma unroll
                for (int nh = 0; nh < 2; nh++)
#pragma unroll
                    for (int s = 0; s < 2; s++) {
                        int nj = nh * 2 + s;
                        mma16816(acc[mi][nj], ah[mi], &bh[nh][s * 2]);
                        mma16816(acc[mi][nj], ah[mi], &bl[nh][s * 2]);
                        mma16816(acc[mi][nj], al[mi], &bh[nh][s * 2]);
                    }
        }
        cpwait1();
        __syncthreads();
    }

#pragma unroll
    for (int mi = 0; mi < 2; mi++)
#pragma unroll
        for (int half = 0; half < 2; half++) {
            int m = wm + mi * 16 + (lane >> 2) + half * 8;
            int r = row0 + m;
            if (r < cnt) {
                int tok = g_idx[e][r];
                float w = g_cw[e][r];
                float* o = out + (size_t)tok * H + col0 + wn + (lane & 3) * 2;
#pragma unroll
                for (int nj = 0; nj < 4; nj++) {
                    atomicAdd(&o[nj * 8 + 0], w * acc[mi][nj][half * 2 + 0]);
                    atomicAdd(&o[nj * 8 + 1], w * acc[mi][nj][half * 2 + 1]);
                }
            }
        }
}

// ---------------------------------------------------------------------------
__global__ void finalize_kernel(float* __restrict__ out, int out_size) {
    if (threadIdx.x == 0 && blockIdx.x == 0) {
        float bal = 0.f;
#pragma unroll
        for (int e = 0; e < E; e++)
            bal += ((float)g_cnt[e] / (float)(T * TK)) * (g_sumprob[e] / (float)T);
        out[out_size - 2] = (float)E * bal;
        out[out_size - 1] = g_zsum / (float)T;
    }
}

// ---------------------------------------------------------------------------
extern "C" void kernel_launch(void* const* d_in, const int* in_sizes, int n_in,
                              void* d_out, int out_size) {
    const float* x  = (const float*)d_in[0];
    const float* gw = (const float*)d_in[1];
    const float* wg = (const float*)d_in[2];
    const float* wu = (const float*)d_in[3];
    const float* wd = (const float*)d_in[4];
    float* out = (float*)d_out;

    cudaFuncSetAttribute(gemm1_tc, cudaFuncAttributeMaxDynamicSharedMemorySize, SMEM1);
    cudaFuncSetAttribute(gemm2_tc, cudaFuncAttributeMaxDynamicSharedMemorySize, SMEM2);

    zero_kernel<<<512, 256>>>(out);

    size_t nw = (size_t)E * H * F / 4;
    convert_kernel<<<2048, 256>>>((const float4*)wg, nw, 0);
    convert_kernel<<<2048, 256>>>((const float4*)wu, nw, 1);
    convert_kernel<<<2048, 256>>>((const float4*)wd, nw, 2);
    convert_kernel<<<1024, 256>>>((const float4*)x, (size_t)T * H / 4, 3);

    router_kernel<<<T / 8, 256>>>(x, gw);

    dim3 g1(F / BN1, T / BM, E);   // 64 x 64 x 8
    dim3 g2(H / BN2, T / BM, E);   // 8 x 64 x 8
    gemm1_tc<<<g1, NT, SMEM1>>>();
    gemm2_tc<<<g2, NT, SMEM2>>>(out);

    finalize_kernel<<<1, 32>>>(out, out_size);
}

// round 12
// speedup vs baseline: 1.0276x; 1.0276x over previous
#include <cuda_runtime.h>
#include <cuda_bf16.h>
#include <stdint.h>
#include <math.h>

#define H 1024
#define F 4096
#define E 8
#define TK 2
#define T 8192

#define BM 128
#define BN 128            // per-matrix N tile (both gemms)
#define BK 32
#define NSTAGE 3
#define NT 256

#define APITCH 40
#define BPITCH 136
#define A_BYTES (BM * APITCH * 2)      // 10240
#define B_BYTES (BK * BPITCH * 2)      // 8704
#define STAGE1  (2 * A_BYTES + 4 * B_BYTES)   // 55296 (Ah,Al,Bgh,Bgl,Buh,Bul)
#define STAGE2  (2 * A_BYTES + 2 * B_BYTES)   // 37888
#define SMEM1   (NSTAGE * STAGE1 + 512)       // 166400
#define SMEM2   (NSTAGE * STAGE2)             // 113664

// ---- device scratch ----
__device__ int   g_cnt[E];
__device__ int   g_idx[E][T];
__device__ float g_cw[E][T];
__device__ float g_sumprob[E];
__device__ float g_zsum;

__device__ __align__(16) __nv_bfloat16 g_xh[(size_t)T * H];
__device__ __align__(16) __nv_bfloat16 g_xl[(size_t)T * H];
__device__ __align__(16) __nv_bfloat16 g_wgh[(size_t)E * H * F];
__device__ __align__(16) __nv_bfloat16 g_wgl[(size_t)E * H * F];
__device__ __align__(16) __nv_bfloat16 g_wuh[(size_t)E * H * F];
__device__ __align__(16) __nv_bfloat16 g_wul[(size_t)E * H * F];
__device__ __align__(16) __nv_bfloat16 g_wdh[(size_t)E * F * H];
__device__ __align__(16) __nv_bfloat16 g_wdl[(size_t)E * F * H];
// expert e owns rows [e*T, e*T+cnt[e])
__device__ __align__(16) __nv_bfloat16 g_hh[(size_t)E * T * F];
__device__ __align__(16) __nv_bfloat16 g_hl[(size_t)E * T * F];

// ---------------------------------------------------------------------------
__device__ __forceinline__ unsigned sptr(const void* p) {
    return (unsigned)__cvta_generic_to_shared(p);
}
__device__ __forceinline__ void ldsm4(unsigned* r, unsigned a) {
    asm volatile("ldmatrix.sync.aligned.m8n8.x4.shared.b16 {%0,%1,%2,%3}, [%4];"
                 : "=r"(r[0]), "=r"(r[1]), "=r"(r[2]), "=r"(r[3]) : "r"(a));
}
__device__ __forceinline__ void ldsm4t(unsigned* r, unsigned a) {
    asm volatile("ldmatrix.sync.aligned.m8n8.x4.trans.shared.b16 {%0,%1,%2,%3}, [%4];"
                 : "=r"(r[0]), "=r"(r[1]), "=r"(r[2]), "=r"(r[3]) : "r"(a));
}
__device__ __forceinline__ void mma16816(float* d, const unsigned* a, const unsigned* b) {
    asm volatile("mma.sync.aligned.m16n8k16.row.col.f32.bf16.bf16.f32 "
                 "{%0,%1,%2,%3},{%4,%5,%6,%7},{%8,%9},{%0,%1,%2,%3};"
                 : "+f"(d[0]), "+f"(d[1]), "+f"(d[2]), "+f"(d[3])
                 : "r"(a[0]), "r"(a[1]), "r"(a[2]), "r"(a[3]), "r"(b[0]), "r"(b[1]));
}
__device__ __forceinline__ void split2(float x, float y, unsigned& hi, unsigned& lo) {
    __nv_bfloat16 hx = __float2bfloat16(x);
    __nv_bfloat16 hy = __float2bfloat16(y);
    __nv_bfloat16 lx = __float2bfloat16(x - __bfloat162float(hx));
    __nv_bfloat16 ly = __float2bfloat16(y - __bfloat162float(hy));
    __nv_bfloat162 h = __halves2bfloat162(hx, hy);
    __nv_bfloat162 l = __halves2bfloat162(lx, ly);
    hi = *reinterpret_cast<unsigned*>(&h);
    lo = *reinterpret_cast<unsigned*>(&l);
}
__device__ __forceinline__ void cpasync16(unsigned dst, const void* src, int sz) {
    asm volatile("cp.async.cg.shared.global [%0], [%1], 16, %2;\n"
                 :: "r"(dst), "l"(src), "r"(sz));
}
__device__ __forceinline__ void cpcommit() { asm volatile("cp.async.commit_group;\n"); }
__device__ __forceinline__ void cpwait1()  { asm volatile("cp.async.wait_group 1;\n"); }

// ---------------------------------------------------------------------------
__global__ void convert_kernel(const float4* __restrict__ src, size_t n4, int which) {
    uint2* dh; uint2* dl;
    if (which == 0)      { dh = (uint2*)g_wgh; dl = (uint2*)g_wgl; }
    else if (which == 1) { dh = (uint2*)g_wuh; dl = (uint2*)g_wul; }
    else if (which == 2) { dh = (uint2*)g_wdh; dl = (uint2*)g_wdl; }
    else                 { dh = (uint2*)g_xh;  dl = (uint2*)g_xl;  }
    size_t stride = (size_t)gridDim.x * blockDim.x;
    for (size_t i = (size_t)blockIdx.x * blockDim.x + threadIdx.x; i < n4; i += stride) {
        float4 v = src[i];
        unsigned h0, l0, h1, l1;
        split2(v.x, v.y, h0, l0);
        split2(v.z, v.w, h1, l1);
        dh[i] = make_uint2(h0, h1);
        dl[i] = make_uint2(l0, l1);
    }
}

__global__ void zero_kernel(float* __restrict__ out) {
    size_t n = (size_t)T * H;
    size_t stride = (size_t)gridDim.x * blockDim.x;
    for (size_t i = (size_t)blockIdx.x * blockDim.x + threadIdx.x; i < n; i += stride)
        out[i] = 0.f;
    if (blockIdx.x == 0 && threadIdx.x < E) {
        g_cnt[threadIdx.x] = 0;
        g_sumprob[threadIdx.x] = 0.f;
    }
    if (blockIdx.x == 0 && threadIdx.x == E) g_zsum = 0.f;
}

__global__ void router_kernel(const float* __restrict__ x,
                              const float* __restrict__ gw) {
    int warp = threadIdx.x >> 5;
    int lane = threadIdx.x & 31;
    int t = blockIdx.x * (blockDim.x >> 5) + warp;
    if (t >= T) return;

    const float* xr = x + (size_t)t * H;
    float acc[E];
#pragma unroll
    for (int e = 0; e < E; e++) acc[e] = 0.f;
    for (int h = lane; h < H; h += 32) {
        float xv = xr[h];
#pragma unroll
        for (int e = 0; e < E; e++) acc[e] += xv * gw[h * E + e];
    }
#pragma unroll
    for (int off = 16; off; off >>= 1) {
#pragma unroll
        for (int e = 0; e < E; e++)
            acc[e] += __shfl_down_sync(0xffffffffu, acc[e], off);
    }
    if (lane == 0) {
        float m = acc[0];
#pragma unroll
        for (int e = 1; e < E; e++) m = fmaxf(m, acc[e]);
        float p[E], s = 0.f;
#pragma unroll
        for (int e = 0; e < E; e++) { p[e] = __expf(acc[e] - m); s += p[e]; }
        float inv = 1.f / s;
        float lse = m + logf(s);
        atomicAdd(&g_zsum, lse * lse);
        int i1 = 0; float p1 = -1.f;
#pragma unroll
        for (int e = 0; e < E; e++) {
            float pe = p[e] * inv;
            p[e] = pe;
            atomicAdd(&g_sumprob[e], pe);
            if (pe > p1) { p1 = pe; i1 = e; }
        }
        int i2 = -1; float p2 = -1.f;
#pragma unroll
        for (int e = 0; e < E; e++)
            if (e != i1 && p[e] > p2) { p2 = p[e]; i2 = e; }
        float rs = 1.f / (p1 + p2);
        int pos1 = atomicAdd(&g_cnt[i1], 1);
        g_idx[i1][pos1] = t; g_cw[i1][pos1] = p1 * rs;
        int pos2 = atomicAdd(&g_cnt[i2], 1);
        g_idx[i2][pos2] = t; g_cw[i2][pos2] = p2 * rs;
    }
}

// ---------------------------------------------------------------------------
// GEMM1 stage loader: A 128x32 hi/lo (gather), B gate/up 32x128 hi/lo
__device__ __forceinline__ void issue1(int k0, unsigned buf, const int* __restrict__ ridx,
                                       const __nv_bfloat16* __restrict__ wgh,
                                       const __nv_bfloat16* __restrict__ wgl,
                                       const __nv_bfloat16* __restrict__ wuh,
                                       const __nv_bfloat16* __restrict__ wul,
                                       int col0, int tid) {
#pragma unroll
    for (int i = 0; i < 2; i++) {
        int idx = tid + i * 256; int r = idx >> 2, c = idx & 3;
        int tok = ridx[r];
        int sz = (tok >= 0) ? 16 : 0;
        size_t so = (size_t)(tok >= 0 ? tok : 0) * H + k0 + c * 8;
        unsigned da = buf + r * (APITCH * 2) + c * 16;
        cpasync16(da,           g_xh + so, sz);
        cpasync16(da + A_BYTES, g_xl + so, sz);
    }
#pragma unroll
    for (int i = 0; i < 2; i++) {
        int idx = tid + i * 256; int r = idx >> 4, c = idx & 15;
        size_t so = (size_t)(k0 + r) * F + col0 + c * 8;
        unsigned db = buf + 2 * A_BYTES + r * (BPITCH * 2) + c * 16;
        cpasync16(db,               wgh + so, 16);
        cpasync16(db + B_BYTES,     wgl + so, 16);
        cpasync16(db + 2 * B_BYTES, wuh + so, 16);
        cpasync16(db + 3 * B_BYTES, wul + so, 16);
    }
}

// GEMM1: CTA 128 x (gate 128 | up 128). 8 warps 2m x 4n-eff, warp tile 64x64.
__global__ __launch_bounds__(NT, 1) void gemm1_tc() {
    int e = blockIdx.z;
    int cnt = g_cnt[e];
    int row0 = blockIdx.x * BM;
    if (row0 >= cnt) return;
    int col0 = blockIdx.y * BN;

    const __nv_bfloat16* wgh = g_wgh + (size_t)e * H * F;
    const __nv_bfloat16* wgl = g_wgl + (size_t)e * H * F;
    const __nv_bfloat16* wuh = g_wuh + (size_t)e * H * F;
    const __nv_bfloat16* wul = g_wul + (size_t)e * H * F;

    extern __shared__ char smem[];
    unsigned sbase = sptr(smem);
    int* ridx = (int*)(smem + NSTAGE * STAGE1);

    int tid = threadIdx.x;
    int lane = tid & 31, wid = tid >> 5;
    int wm2 = (wid & 1) * 64;          // 2 m-groups of 64 rows
    int ng  = wid >> 1;                 // 4 n-groups
    int mat = ng >> 1;                  // 0 = gate, 1 = up
    int wn  = (ng & 1) * 64;            // 64 cols within the matrix

    if (tid < BM) { int r = row0 + tid; ridx[tid] = (r < cnt) ? g_idx[e][r] : -1; }
    __syncthreads();

    float acc[4][8][4];
#pragma unroll
    for (int a = 0; a < 4; a++)
#pragma unroll
        for (int b = 0; b < 8; b++)
#pragma unroll
            for (int c = 0; c < 4; c++) acc[a][b][c] = 0.f;

    const int NK = H / BK;   // 32
#pragma unroll
    for (int s = 0; s < NSTAGE - 1; s++) {
        issue1(s * BK, sbase + s * STAGE1, ridx, wgh, wgl, wuh, wul, col0, tid);
        cpcommit();
    }
    cpwait1();
    __syncthreads();

    for (int kt = 0; kt < NK; kt++) {
        int kn = kt + NSTAGE - 1;
        if (kn < NK)
            issue1(kn * BK, sbase + (kn % NSTAGE) * STAGE1, ridx, wgh, wgl, wuh, wul, col0, tid);
        cpcommit();

        unsigned sb = sbase + (kt % NSTAGE) * STAGE1;
        unsigned bbase = sb + 2 * A_BYTES + mat * (2 * B_BYTES);
#pragma unroll
        for (int ks = 0; ks < 2; ks++) {
            unsigned ah[4][4], al[4][4];
            int ar = wm2 + (lane & 15);
            int ac = ks * 16 + (lane >> 4) * 8;
#pragma unroll
            for (int mi = 0; mi < 4; mi++) {
                unsigned aoff = ((ar + mi * 16) * APITCH + ac) * 2;
                ldsm4(ah[mi], sb + aoff);
                ldsm4(al[mi], sb + A_BYTES + aoff);
            }
            int br = ks * 16 + (lane & 15), bc = wn + (lane >> 4) * 8;
            unsigned bh[4][4], bl[4][4];
#pragma unroll
            for (int nh = 0; nh < 4; nh++) {
                unsigned boff = (br * BPITCH + bc + nh * 16) * 2;
                ldsm4t(bh[nh], bbase + boff);
                ldsm4t(bl[nh], bbase + B_BYTES + boff);
            }
#pragma unroll
            for (int mi = 0; mi < 4; mi++)
#pragma unroll
                for (int nh = 0; nh < 4; nh++)
#pragma unroll
                    for (int s = 0; s < 2; s++) {
                        int nj = nh * 2 + s;
                        mma16816(acc[mi][nj], ah[mi], &bh[nh][s * 2]);
                        mma16816(acc[mi][nj], ah[mi], &bl[nh][s * 2]);
                        mma16816(acc[mi][nj], al[mi], &bh[nh][s * 2]);
                    }
        }
        cpwait1();
        __syncthreads();
    }

    // epilogue: gate warps -> smem; up warps combine silu(g)*u -> g_hh/g_hl
    __syncthreads();
    float (*sg)[132] = (float(*)[132])smem;   // 128 x 132 floats = 67.6KB
    if (mat == 0) {
#pragma unroll
        for (int mi = 0; mi < 4; mi++)
#pragma unroll
            for (int nj = 0; nj < 8; nj++)
#pragma unroll
                for (int k = 0; k < 4; k++) {
                    int m = wm2 + mi * 16 + (lane >> 2) + (k >> 1) * 8;
                    int n = wn + nj * 8 + (lane & 3) * 2 + (k & 1);
                    sg[m][n] = acc[mi][nj][k];
                }
    }
    __syncthreads();
    if (mat == 1) {
#pragma unroll
        for (int mi = 0; mi < 4; mi++)
#pragma unroll
            for (int half = 0; half < 2; half++) {
                int m = wm2 + mi * 16 + (lane >> 2) + half * 8;
                int r = row0 + m;
                if (r < cnt) {
                    size_t base = ((size_t)e * T + r) * F + col0 + wn + (lane & 3) * 2;
#pragma unroll
                    for (int nj = 0; nj < 8; nj++) {
                        int nl = wn + nj * 8 + (lane & 3) * 2;
                        float g0 = sg[m][nl];
                        float g1 = sg[m][nl + 1];
                        float u0 = acc[mi][nj][half * 2 + 0];
                        float u1 = acc[mi][nj][half * 2 + 1];
                        float h0 = g0 / (1.f + __expf(-g0)) * u0;
                        float h1 = g1 / (1.f + __expf(-g1)) * u1;
                        unsigned hh, hl;
                        split2(h0, h1, hh, hl);
                        *reinterpret_cast<unsigned*>(g_hh + base + nj * 8) = hh;
                        *reinterpret_cast<unsigned*>(g_hl + base + nj * 8) = hl;
                    }
                }
            }
    }
}

// ---------------------------------------------------------------------------
// GEMM2 stage loader: A 128x32 hi/lo (linear) + Wd 32x128 hi/lo
__device__ __forceinline__ void issue2(int k0, unsigned buf, size_t arow0, int rows,
                                       const __nv_bfloat16* __restrict__ wdh,
                                       const __nv_bfloat16* __restrict__ wdl,
                                       int col0, int tid) {
#pragma unroll
    for (int i = 0; i < 2; i++) {
        int idx = tid + i * 256; int r = idx >> 2, c = idx & 3;
        int sz = (r < rows) ? 16 : 0;
        size_t so = (arow0 + (r < rows ? r : 0)) * F + k0 + c * 8;
        unsigned da = buf + r * (APITCH * 2) + c * 16;
        cpasync16(da,           g_hh + so, sz);
        cpasync16(da + A_BYTES, g_hl + so, sz);
    }
#pragma unroll
    for (int i = 0; i < 2; i++) {
        int idx = tid + i * 256; int r = idx >> 4, c = idx & 15;
        size_t so = (size_t)(k0 + r) * H + col0 + c * 8;
        unsigned db = buf + 2 * A_BYTES + r * (BPITCH * 2) + c * 16;
        cpasync16(db,           wdh + so, 16);
        cpasync16(db + B_BYTES, wdl + so, 16);
    }
}

// GEMM2: CTA 128x128. 8 warps 4m x 2n, warp tile 32x64. Atomic scatter epilogue.
__global__ __launch_bounds__(NT, 1) void gemm2_tc(float* __restrict__ out) {
    int e = blockIdx.z;
    int cnt = g_cnt[e];
    int row0 = blockIdx.x * BM;
    if (row0 >= cnt) return;
    int col0 = blockIdx.y * BN;
    int rows = cnt - row0; if (rows > BM) rows = BM;
    size_t arow0 = (size_t)e * T + row0;

    const __nv_bfloat16* wdh = g_wdh + (size_t)e * F * H;
    const __nv_bfloat16* wdl = g_wdl + (size_t)e * F * H;

    extern __shared__ char smem[];
    unsigned sbase = sptr(smem);

    int tid = threadIdx.x;
    int lane = tid & 31, wid = tid >> 5;
    int wm = (wid & 3) * 32, wn = (wid >> 2) * 64;

    float acc[2][8][4];
#pragma unroll
    for (int b = 0; b < 2; b++)
#pragma unroll
        for (int c = 0; c < 8; c++)
#pragma unroll
            for (int d = 0; d < 4; d++) acc[b][c][d] = 0.f;

    const int NK = F / BK;   // 128
#pragma unroll
    for (int s = 0; s < NSTAGE - 1; s++) {
        issue2(s * BK, sbase + s * STAGE2, arow0, rows, wdh, wdl, col0, tid);
        cpcommit();
    }
    cpwait1();
    __syncthreads();

    for (int kt = 0; kt < NK; kt++) {
        int kn = kt + NSTAGE - 1;
        if (kn < NK)
            issue2(kn * BK, sbase + (kn % NSTAGE) * STAGE2, arow0, rows, wdh, wdl, col0, tid);
        cpcommit();

        unsigned sb = sbase + (kt % NSTAGE) * STAGE2;
        unsigned bbase = sb + 2 * A_BYTES;
#pragma unroll
        for (int ks = 0; ks < 2; ks++) {
            unsigned ah[2][4], al[2][4];
            int ar = wm + (lane & 15);
            int ac = ks * 16 + (lane >> 4) * 8;
#pragma unroll
            for (int mi = 0; mi < 2; mi++) {
                unsigned aoff = ((ar + mi * 16) * APITCH + ac) * 2;
                ldsm4(ah[mi], sb + aoff);
                ldsm4(al[mi], sb + A_BYTES + aoff);
            }
            int br = ks * 16 + (lane & 15), bc = wn + (lane >> 4) * 8;
            unsigned bh[4][4], bl[4][4];
#pragma unroll
            for (int nh = 0; nh < 4; nh++) {
                unsigned boff = (br * BPITCH + bc + nh * 16) * 2;
                ldsm4t(bh[nh], bbase + boff);
                ldsm4t(bl[nh], bbase + B_BYTES + boff);
            }
#pragma unroll
            for (int mi = 0; mi < 2; mi++)
#pragma unroll
                for (int nh = 0; nh < 4; nh++)
#pragma unroll
                    for (int s = 0; s < 2; s++) {
                        int nj = nh * 2 + s;
                        mma16816(acc[mi][nj], ah[mi], &bh[nh][s * 2]);
                        mma16816(acc[mi][nj], ah[mi], &bl[nh][s * 2]);
                        mma16816(acc[mi][nj], al[mi], &bh[nh][s * 2]);
                    }
        }
        cpwait1();
        __syncthreads();
    }

#pragma unroll
    for (int mi = 0; mi < 2; mi++)
#pragma unroll
        for (int half = 0; half < 2; half++) {
            int m = wm + mi * 16 + (lane >> 2) + half * 8;
            int r = row0 + m;
            if (r < cnt) {
                int tok = g_idx[e][r];
                float w = g_cw[e][r];
                float* o = out + (size_t)tok * H + col0 + wn + (lane & 3) * 2;
#pragma unroll
                for (int nj = 0; nj < 8; nj++) {
                    atomicAdd(&o[nj * 8 + 0], w * acc[mi][nj][half * 2 + 0]);
                    atomicAdd(&o[nj * 8 + 1], w * acc[mi][nj][half * 2 + 1]);
                }
            }
        }
}

// ---------------------------------------------------------------------------
__global__ void finalize_kernel(float* __restrict__ out, int out_size) {
    if (threadIdx.x == 0 && blockIdx.x == 0) {
        float bal = 0.f;
#pragma unroll
        for (int e = 0; e < E; e++)
            bal += ((float)g_cnt[e] / (float)(T * TK)) * (g_sumprob[e] / (float)T);
        out[out_size - 2] = (float)E * bal;
        out[out_size - 1] = g_zsum / (float)T;
    }
}

// ---------------------------------------------------------------------------
extern "C" void kernel_launch(void* const* d_in, const int* in_sizes, int n_in,
                              void* d_out, int out_size) {
    const float* x  = (const float*)d_in[0];
    const float* gw = (const float*)d_in[1];
    const float* wg = (const float*)d_in[2];
    const float* wu = (const float*)d_in[3];
    const float* wd = (const float*)d_in[4];
    float* out = (float*)d_out;

    cudaFuncSetAttribute(gemm1_tc, cudaFuncAttributeMaxDynamicSharedMemorySize, SMEM1);
    cudaFuncSetAttribute(gemm2_tc, cudaFuncAttributeMaxDynamicSharedMemorySize, SMEM2);

    zero_kernel<<<512, 256>>>(out);

    size_t nw = (size_t)E * H * F / 4;
    convert_kernel<<<2048, 256>>>((const float4*)wg, nw, 0);
    convert_kernel<<<2048, 256>>>((const float4*)wu, nw, 1);
    convert_kernel<<<2048, 256>>>((const float4*)wd, nw, 2);
    convert_kernel<<<1024, 256>>>((const float4*)x, (size_t)T * H / 4, 3);

    router_kernel<<<T / 8, 256>>>(x, gw);

    // x = row-tiles (fastest): concurrent CTAs share the same weight col-tile in L2
    dim3 g1(T / BM, F / BN, E);   // 64 x 32 x 8
    dim3 g2(T / BM, H / BN, E);   // 64 x 8 x 8
    gemm1_tc<<<g1, NT, SMEM1>>>();
    gemm2_tc<<<g2, NT, SMEM2>>>(out);

    finalize_kernel<<<1, 32>>>(out, out_size);
}

// round 14
// speedup vs baseline: 1.3792x; 1.3421x over previous
#include <cuda_runtime.h>
#include <cuda_fp16.h>
#include <stdint.h>
#include <math.h>

#define H 1024
#define F 4096
#define E 8
#define TK 2
#define T 8192

#define BM 128
#define BN 128            // per-matrix N tile (both gemms)
#define BK 32
#define NSTAGE 3
#define NT 256

#define APITCH 40         // halves per A row (80 B)
#define BPITCH 136        // halves per B row (272 B)
#define A_BYTES (BM * APITCH * 2)      // 10240
#define B_BYTES (BK * BPITCH * 2)      // 8704
#define STAGE1  (2 * A_BYTES + 2 * B_BYTES)   // 37888 (Ah,Al,Bg,Bu)
#define STAGE2  (2 * A_BYTES + B_BYTES)       // 29184 (Ah,Al,Bd)
#define SMEM1   (NSTAGE * STAGE1 + 512)       // 114176
#define SMEM2   (NSTAGE * STAGE2)             // 87552

// ---- device scratch ----
__device__ int   g_cnt[E];
__device__ int   g_idx[E][T];
__device__ float g_cw[E][T];
__device__ float g_sumprob[E];
__device__ float g_zsum;

// activations: fp16 hi/lo. weights: single fp16 (unbiased rn).
__device__ __align__(16) __half g_xh[(size_t)T * H];
__device__ __align__(16) __half g_xl[(size_t)T * H];
__device__ __align__(16) __half g_wg[(size_t)E * H * F];     // [E][H][F] k-major
__device__ __align__(16) __half g_wu[(size_t)E * H * F];
__device__ __align__(16) __half g_wd[(size_t)E * F * H];     // [E][F][H] k-major
// expert e owns rows [e*T, e*T+cnt[e])
__device__ __align__(16) __half g_hh[(size_t)E * T * F];
__device__ __align__(16) __half g_hl[(size_t)E * T * F];

// ---------------------------------------------------------------------------
__device__ __forceinline__ unsigned sptr(const void* p) {
    return (unsigned)__cvta_generic_to_shared(p);
}
__device__ __forceinline__ void ldsm4(unsigned* r, unsigned a) {
    asm volatile("ldmatrix.sync.aligned.m8n8.x4.shared.b16 {%0,%1,%2,%3}, [%4];"
                 : "=r"(r[0]), "=r"(r[1]), "=r"(r[2]), "=r"(r[3]) : "r"(a));
}
__device__ __forceinline__ void ldsm4t(unsigned* r, unsigned a) {
    asm volatile("ldmatrix.sync.aligned.m8n8.x4.trans.shared.b16 {%0,%1,%2,%3}, [%4];"
                 : "=r"(r[0]), "=r"(r[1]), "=r"(r[2]), "=r"(r[3]) : "r"(a));
}
__device__ __forceinline__ void mma16816(float* d, const unsigned* a, const unsigned* b) {
    asm volatile("mma.sync.aligned.m16n8k16.row.col.f32.f16.f16.f32 "
                 "{%0,%1,%2,%3},{%4,%5,%6,%7},{%8,%9},{%0,%1,%2,%3};"
                 : "+f"(d[0]), "+f"(d[1]), "+f"(d[2]), "+f"(d[3])
                 : "r"(a[0]), "r"(a[1]), "r"(a[2]), "r"(a[3]), "r"(b[0]), "r"(b[1]));
}
// split two fp32 into packed fp16x2 hi + fp16x2 residual (exact residual in fp32)
__device__ __forceinline__ void split2h(float x, float y, unsigned& hi, unsigned& lo) {
    __half hx = __float2half_rn(x);
    __half hy = __float2half_rn(y);
    __half lx = __float2half_rn(x - __half2float(hx));
    __half ly = __float2half_rn(y - __half2float(hy));
    __half2 h = __halves2half2(hx, hy);
    __half2 l = __halves2half2(lx, ly);
    hi = *reinterpret_cast<unsigned*>(&h);
    lo = *reinterpret_cast<unsigned*>(&l);
}
__device__ __forceinline__ void cpasync16(unsigned dst, const void* src, int sz) {
    asm volatile("cp.async.cg.shared.global [%0], [%1], 16, %2;\n"
                 :: "r"(dst), "l"(src), "r"(sz));
}
__device__ __forceinline__ void cpcommit() { asm volatile("cp.async.commit_group;\n"); }
__device__ __forceinline__ void cpwait1()  { asm volatile("cp.async.wait_group 1;\n"); }

// ---------------------------------------------------------------------------
// weights: fp32 -> single fp16 (rn)
__global__ void convert_w(const float4* __restrict__ src, size_t n4, int which) {
    uint2* d;
    if (which == 0)      d = (uint2*)g_wg;
    else if (which == 1) d = (uint2*)g_wu;
    else                 d = (uint2*)g_wd;
    size_t stride = (size_t)gridDim.x * blockDim.x;
    for (size_t i = (size_t)blockIdx.x * blockDim.x + threadIdx.x; i < n4; i += stride) {
        float4 v = src[i];
        __half2 a = __floats2half2_rn(v.x, v.y);
        __half2 b = __floats2half2_rn(v.z, v.w);
        d[i] = make_uint2(*reinterpret_cast<unsigned*>(&a),
                          *reinterpret_cast<unsigned*>(&b));
    }
}

// x: fp32 -> fp16 hi/lo
__global__ void convert_x(const float4* __restrict__ src, size_t n4) {
    uint2* dh = (uint2*)g_xh; uint2* dl = (uint2*)g_xl;
    size_t stride = (size_t)gridDim.x * blockDim.x;
    for (size_t i = (size_t)blockIdx.x * blockDim.x + threadIdx.x; i < n4; i += stride) {
        float4 v = src[i];
        unsigned h0, l0, h1, l1;
        split2h(v.x, v.y, h0, l0);
        split2h(v.z, v.w, h1, l1);
        dh[i] = make_uint2(h0, h1);
        dl[i] = make_uint2(l0, l1);
    }
}

__global__ void zero_kernel(float* __restrict__ out) {
    size_t n = (size_t)T * H;
    size_t stride = (size_t)gridDim.x * blockDim.x;
    for (size_t i = (size_t)blockIdx.x * blockDim.x + threadIdx.x; i < n; i += stride)
        out[i] = 0.f;
    if (blockIdx.x == 0 && threadIdx.x < E) {
        g_cnt[threadIdx.x] = 0;
        g_sumprob[threadIdx.x] = 0.f;
    }
    if (blockIdx.x == 0 && threadIdx.x == E) g_zsum = 0.f;
}

__global__ void router_kernel(const float* __restrict__ x,
                              const float* __restrict__ gw) {
    int warp = threadIdx.x >> 5;
    int lane = threadIdx.x & 31;
    int t = blockIdx.x * (blockDim.x >> 5) + warp;
    if (t >= T) return;

    const float* xr = x + (size_t)t * H;
    float acc[E];
#pragma unroll
    for (int e = 0; e < E; e++) acc[e] = 0.f;
    for (int h = lane; h < H; h += 32) {
        float xv = xr[h];
#pragma unroll
        for (int e = 0; e < E; e++) acc[e] += xv * gw[h * E + e];
    }
#pragma unroll
    for (int off = 16; off; off >>= 1) {
#pragma unroll
        for (int e = 0; e < E; e++)
            acc[e] += __shfl_down_sync(0xffffffffu, acc[e], off);
    }
    if (lane == 0) {
        float m = acc[0];
#pragma unroll
        for (int e = 1; e < E; e++) m = fmaxf(m, acc[e]);
        float p[E], s = 0.f;
#pragma unroll
        for (int e = 0; e < E; e++) { p[e] = __expf(acc[e] - m); s += p[e]; }
        float inv = 1.f / s;
        float lse = m + logf(s);
        atomicAdd(&g_zsum, lse * lse);
        int i1 = 0; float p1 = -1.f;
#pragma unroll
        for (int e = 0; e < E; e++) {
            float pe = p[e] * inv;
            p[e] = pe;
            atomicAdd(&g_sumprob[e], pe);
            if (pe > p1) { p1 = pe; i1 = e; }
        }
        int i2 = -1; float p2 = -1.f;
#pragma unroll
        for (int e = 0; e < E; e++)
            if (e != i1 && p[e] > p2) { p2 = p[e]; i2 = e; }
        float rs = 1.f / (p1 + p2);
        int pos1 = atomicAdd(&g_cnt[i1], 1);
        g_idx[i1][pos1] = t; g_cw[i1][pos1] = p1 * rs;
        int pos2 = atomicAdd(&g_cnt[i2], 1);
        g_idx[i2][pos2] = t; g_cw[i2][pos2] = p2 * rs;
    }
}

// ---------------------------------------------------------------------------
// GEMM1 stage loader: A 128x32 fp16 hi/lo (gather), B gate/up 32x128 fp16
__device__ __forceinline__ void issue1(int k0, unsigned buf, const int* __restrict__ ridx,
                                       const __half* __restrict__ wg,
                                       const __half* __restrict__ wu,
                                       int col0, int tid) {
#pragma unroll
    for (int i = 0; i < 2; i++) {
        int idx = tid + i * 256; int r = idx >> 2, c = idx & 3;
        int tok = ridx[r];
        int sz = (tok >= 0) ? 16 : 0;
        size_t so = (size_t)(tok >= 0 ? tok : 0) * H + k0 + c * 8;
        unsigned da = buf + r * (APITCH * 2) + c * 16;
        cpasync16(da,           g_xh + so, sz);
        cpasync16(da + A_BYTES, g_xl + so, sz);
    }
#pragma unroll
    for (int i = 0; i < 2; i++) {
        int idx = tid + i * 256; int r = idx >> 4, c = idx & 15;
        size_t so = (size_t)(k0 + r) * F + col0 + c * 8;
        unsigned db = buf + 2 * A_BYTES + r * (BPITCH * 2) + c * 16;
        cpasync16(db,           wg + so, 16);
        cpasync16(db + B_BYTES, wu + so, 16);
    }
}

// GEMM1: CTA 128 x (gate 128 | up 128). 8 warps: 2m x 2n x 2mat, warp tile 64x64.
// 2-pass fp16: (Ah + Al) @ Bh
__global__ __launch_bounds__(NT, 1) void gemm1_tc() {
    int e = blockIdx.z;
    int cnt = g_cnt[e];
    int row0 = blockIdx.x * BM;
    if (row0 >= cnt) return;
    int col0 = blockIdx.y * BN;

    const __half* wg = g_wg + (size_t)e * H * F;
    const __half* wu = g_wu + (size_t)e * H * F;

    extern __shared__ char smem[];
    unsigned sbase = sptr(smem);
    int* ridx = (int*)(smem + NSTAGE * STAGE1);

    int tid = threadIdx.x;
    int lane = tid & 31, wid = tid >> 5;
    int wm2 = (wid & 1) * 64;
    int ng  = wid >> 1;
    int mat = ng >> 1;                  // 0 = gate, 1 = up
    int wn  = (ng & 1) * 64;

    if (tid < BM) { int r = row0 + tid; ridx[tid] = (r < cnt) ? g_idx[e][r] : -1; }
    __syncthreads();

    float acc[4][8][4];
#pragma unroll
    for (int a = 0; a < 4; a++)
#pragma unroll
        for (int b = 0; b < 8; b++)
#pragma unroll
            for (int c = 0; c < 4; c++) acc[a][b][c] = 0.f;

    const int NK = H / BK;   // 32
#pragma unroll
    for (int s = 0; s < NSTAGE - 1; s++) {
        issue1(s * BK, sbase + s * STAGE1, ridx, wg, wu, col0, tid);
        cpcommit();
    }
    cpwait1();
    __syncthreads();

    for (int kt = 0; kt < NK; kt++) {
        int kn = kt + NSTAGE - 1;
        if (kn < NK)
            issue1(kn * BK, sbase + (kn % NSTAGE) * STAGE1, ridx, wg, wu, col0, tid);
        cpcommit();

        unsigned sb = sbase + (kt % NSTAGE) * STAGE1;
        unsigned bbase = sb + 2 * A_BYTES + mat * B_BYTES;
#pragma unroll
        for (int ks = 0; ks < 2; ks++) {
            unsigned ah[4][4], al[4][4];
            int ar = wm2 + (lane & 15);
            int ac = ks * 16 + (lane >> 4) * 8;
#pragma unroll
            for (int mi = 0; mi < 4; mi++) {
                unsigned aoff = ((ar + mi * 16) * APITCH + ac) * 2;
                ldsm4(ah[mi], sb + aoff);
                ldsm4(al[mi], sb + A_BYTES + aoff);
            }
            int br = ks * 16 + (lane & 15), bc = wn + (lane >> 4) * 8;
            unsigned bh[4][4];
#pragma unroll
            for (int nh = 0; nh < 4; nh++) {
                unsigned boff = (br * BPITCH + bc + nh * 16) * 2;
                ldsm4t(bh[nh], bbase + boff);
            }
#pragma unroll
            for (int mi = 0; mi < 4; mi++)
#pragma unroll
                for (int nh = 0; nh < 4; nh++)
#pragma unroll
                    for (int s = 0; s < 2; s++) {
                        int nj = nh * 2 + s;
                        mma16816(acc[mi][nj], ah[mi], &bh[nh][s * 2]);
                        mma16816(acc[mi][nj], al[mi], &bh[nh][s * 2]);
                    }
        }
        cpwait1();
        __syncthreads();
    }

    // epilogue: gate warps -> smem; up warps combine silu(g)*u -> g_hh/g_hl
    __syncthreads();
    float (*sg)[132] = (float(*)[132])smem;   // 128 x 132 floats = 67.6KB
    if (mat == 0) {
#pragma unroll
        for (int mi = 0; mi < 4; mi++)
#pragma unroll
            for (int nj = 0; nj < 8; nj++)
#pragma unroll
                for (int k = 0; k < 4; k++) {
                    int m = wm2 + mi * 16 + (lane >> 2) + (k >> 1) * 8;
                    int n = wn + nj * 8 + (lane & 3) * 2 + (k & 1);
                    sg[m][n] = acc[mi][nj][k];
                }
    }
    __syncthreads();
    if (mat == 1) {
#pragma unroll
        for (int mi = 0; mi < 4; mi++)
#pragma unroll
            for (int half = 0; half < 2; half++) {
                int m = wm2 + mi * 16 + (lane >> 2) + half * 8;
                int r = row0 + m;
                if (r < cnt) {
                    size_t base = ((size_t)e * T + r) * F + col0 + wn + (lane & 3) * 2;
#pragma unroll
                    for (int nj = 0; nj < 8; nj++) {
                        int nl = wn + nj * 8 + (lane & 3) * 2;
                        float g0 = sg[m][nl];
                        float g1 = sg[m][nl + 1];
                        float u0 = acc[mi][nj][half * 2 + 0];
                        float u1 = acc[mi][nj][half * 2 + 1];
                        float h0 = g0 / (1.f + __expf(-g0)) * u0;
                        float h1 = g1 / (1.f + __expf(-g1)) * u1;
                        unsigned hh, hl;
                        split2h(h0, h1, hh, hl);
                        *reinterpret_cast<unsigned*>(g_hh + base + nj * 8) = hh;
                        *reinterpret_cast<unsigned*>(g_hl + base + nj * 8) = hl;
                    }
                }
            }
    }
}

// ---------------------------------------------------------------------------
// GEMM2 stage loader: A 128x32 fp16 hi/lo (linear) + Wd 32x128 fp16
__device__ __forceinline__ void issue2(int k0, unsigned buf, size_t arow0, int rows,
                                       const __half* __restrict__ wd,
                                       int col0, int tid) {
#pragma unroll
    for (int i = 0; i < 2; i++) {
        int idx = tid + i * 256; int r = idx >> 2, c = idx & 3;
        int sz = (r < rows) ? 16 : 0;
        size_t so = (arow0 + (r < rows ? r : 0)) * F + k0 + c * 8;
        unsigned da = buf + r * (APITCH * 2) + c * 16;
        cpasync16(da,           g_hh + so, sz);
        cpasync16(da + A_BYTES, g_hl + so, sz);
    }
#pragma unroll
    for (int i = 0; i < 2; i++) {
        int idx = tid + i * 256; int r = idx >> 4, c = idx & 15;
        size_t so = (size_t)(k0 + r) * H + col0 + c * 8;
        cpasync16(buf + 2 * A_BYTES + r * (BPITCH * 2) + c * 16, wd + so, 16);
    }
}

// GEMM2: CTA 128x128. 8 warps 4m x 2n, warp tile 32x64. Atomic scatter epilogue.
__global__ __launch_bounds__(NT, 1) void gemm2_tc(float* __restrict__ out) {
    int e = blockIdx.z;
    int cnt = g_cnt[e];
    int row0 = blockIdx.x * BM;
    if (row0 >= cnt) return;
    int col0 = blockIdx.y * BN;
    int rows = cnt - row0; if (rows > BM) rows = BM;
    size_t arow0 = (size_t)e * T + row0;

    const __half* wd = g_wd + (size_t)e * F * H;

    extern __shared__ char smem[];
    unsigned sbase = sptr(smem);

    int tid = threadIdx.x;
    int lane = tid & 31, wid = tid >> 5;
    int wm = (wid & 3) * 32, wn = (wid >> 2) * 64;

    float acc[2][8][4];
#pragma unroll
    for (int b = 0; b < 2; b++)
#pragma unroll
        for (int c = 0; c < 8; c++)
#pragma unroll
            for (int d = 0; d < 4; d++) acc[b][c][d] = 0.f;

    const int NK = F / BK;   // 128
#pragma unroll
    for (int s = 0; s < NSTAGE - 1; s++) {
        issue2(s * BK, sbase + s * STAGE2, arow0, rows, wd, col0, tid);
        cpcommit();
    }
    cpwait1();
    __syncthreads();

    for (int kt = 0; kt < NK; kt++) {
        int kn = kt + NSTAGE - 1;
        if (kn < NK)
            issue2(kn * BK, sbase + (kn % NSTAGE) * STAGE2, arow0, rows, wd, col0, tid);
        cpcommit();

        unsigned sb = sbase + (kt % NSTAGE) * STAGE2;
        unsigned bbase = sb + 2 * A_BYTES;
#pragma unroll
        for (int ks = 0; ks < 2; ks++) {
            unsigned ah[2][4], al[2][4];
            int ar = wm + (lane & 15);
            int ac = ks * 16 + (lane >> 4) * 8;
#pragma unroll
            for (int mi = 0; mi < 2; mi++) {
                unsigned aoff = ((ar + mi * 16) * APITCH + ac) * 2;
                ldsm4(ah[mi], sb + aoff);
                ldsm4(al[mi], sb + A_BYTES + aoff);
            }
            int br = ks * 16 + (lane & 15), bc = wn + (lane >> 4) * 8;
            unsigned bh[4][4];
#pragma unroll
            for (int nh = 0; nh < 4; nh++) {
                unsigned boff = (br * BPITCH + bc + nh * 16) * 2;
                ldsm4t(bh[nh], bbase + boff);
            }
#pragma unroll
            for (int mi = 0; mi < 2; mi++)
#pragma unroll
                for (int nh = 0; nh < 4; nh++)
#pragma unroll
                    for (int s = 0; s < 2; s++) {
                        int nj = nh * 2 + s;
                        mma16816(acc[mi][nj], ah[mi], &bh[nh][s * 2]);
                        mma16816(acc[mi][nj], al[mi], &bh[nh][s * 2]);
                    }
        }
        cpwait1();
        __syncthreads();
    }

#pragma unroll
    for (int mi = 0; mi < 2; mi++)
#pragma unroll
        for (int half = 0; half < 2; half++) {
            int m = wm + mi * 16 + (lane >> 2) + half * 8;
            int r = row0 + m;
            if (r < cnt) {
                int tok = g_idx[e][r];
                float w = g_cw[e][r];
                float* o = out + (size_t)tok * H + col0 + wn + (lane & 3) * 2;
#pragma unroll
                for (int nj = 0; nj < 8; nj++) {
                    atomicAdd(&o[nj * 8 + 0], w * acc[mi][nj][half * 2 + 0]);
                    atomicAdd(&o[nj * 8 + 1], w * acc[mi][nj][half * 2 + 1]);
                }
            }
        }
}

// ---------------------------------------------------------------------------
__global__ void finalize_kernel(float* __restrict__ out, int out_size) {
    if (threadIdx.x == 0 && blockIdx.x == 0) {
        float bal = 0.f;
#pragma unroll
        for (int e = 0; e < E; e++)
            bal += ((float)g_cnt[e] / (float)(T * TK)) * (g_sumprob[e] / (float)T);
        out[out_size - 2] = (float)E * bal;
        out[out_size - 1] = g_zsum / (float)T;
    }
}

// ---------------------------------------------------------------------------
extern "C" void kernel_launch(void* const* d_in, const int* in_sizes, int n_in,
                              void* d_out, int out_size) {
    const float* x  = (const float*)d_in[0];
    const float* gw = (const float*)d_in[1];
    const float* wg = (const float*)d_in[2];   // [E][H][F]
    const float* wu = (const float*)d_in[3];   // [E][H][F]
    const float* wd = (const float*)d_in[4];   // [E][F][H]
    float* out = (float*)d_out;

    cudaFuncSetAttribute(gemm1_tc, cudaFuncAttributeMaxDynamicSharedMemorySize, SMEM1);
    cudaFuncSetAttribute(gemm2_tc, cudaFuncAttributeMaxDynamicSharedMemorySize, SMEM2);

    zero_kernel<<<512, 256>>>(out);

    size_t nw = (size_t)E * H * F / 4;
    convert_w<<<2048, 256>>>((const float4*)wg, nw, 0);
    convert_w<<<2048, 256>>>((const float4*)wu, nw, 1);
    convert_w<<<2048, 256>>>((const float4*)wd, nw, 2);
    convert_x<<<1024, 256>>>((const float4*)x, (size_t)T * H / 4);

    router_kernel<<<T / 8, 256>>>(x, gw);

    dim3 g1(T / BM, F / BN, E);   // 64 x 32 x 8
    dim3 g2(T / BM, H / BN, E);   // 64 x 8 x 8
    gemm1_tc<<<g1, NT, SMEM1>>>();
    gemm2_tc<<<g2, NT, SMEM2>>>(out);

    finalize_kernel<<<1, 32>>>(out, out_size);
}

// round 15
// speedup vs baseline: 2.0469x; 1.4841x over previous
#include <cuda_runtime.h>
#include <cuda_fp16.h>
#include <stdint.h>
#include <math.h>

#define H 1024
#define F 4096
#define E 8
#define TK 2
#define T 8192

#define BM 128
#define BN 128            // per-matrix N tile (both gemms)
#define BK 32
#define NSTAGE 3
#define NT 256

#define APITCH 40         // halves per A row (80 B)
#define BPITCH 136        // halves per B row (272 B)
#define A_BYTES (BM * APITCH * 2)      // 10240
#define B_BYTES (BK * BPITCH * 2)      // 8704
#define STAGE1  (A_BYTES + 2 * B_BYTES)   // 27648 (A,Bg,Bu)
#define STAGE2  (A_BYTES + B_BYTES)       // 18944 (A,Bd)
#define SMEM1   (NSTAGE * STAGE1 + 512)   // 83456
#define SMEM2   (NSTAGE * STAGE2)         // 56832

// ---- device scratch ----
__device__ int   g_cnt[E];
__device__ int   g_idx[E][T];
__device__ float g_cw[E][T];
__device__ float g_sumprob[E];
__device__ float g_zsum;

// all GEMM operands: single fp16 (rn, unbiased)
__device__ __align__(16) __half g_xf[(size_t)T * H];
__device__ __align__(16) __half g_wg[(size_t)E * H * F];     // [E][H][F] k-major
__device__ __align__(16) __half g_wu[(size_t)E * H * F];
__device__ __align__(16) __half g_wd[(size_t)E * F * H];     // [E][F][H] k-major
// expert e owns rows [e*T, e*T+cnt[e])
__device__ __align__(16) __half g_hf[(size_t)E * T * F];

// ---------------------------------------------------------------------------
__device__ __forceinline__ unsigned sptr(const void* p) {
    return (unsigned)__cvta_generic_to_shared(p);
}
__device__ __forceinline__ void ldsm4(unsigned* r, unsigned a) {
    asm volatile("ldmatrix.sync.aligned.m8n8.x4.shared.b16 {%0,%1,%2,%3}, [%4];"
                 : "=r"(r[0]), "=r"(r[1]), "=r"(r[2]), "=r"(r[3]) : "r"(a));
}
__device__ __forceinline__ void ldsm4t(unsigned* r, unsigned a) {
    asm volatile("ldmatrix.sync.aligned.m8n8.x4.trans.shared.b16 {%0,%1,%2,%3}, [%4];"
                 : "=r"(r[0]), "=r"(r[1]), "=r"(r[2]), "=r"(r[3]) : "r"(a));
}
__device__ __forceinline__ void mma16816(float* d, const unsigned* a, const unsigned* b) {
    asm volatile("mma.sync.aligned.m16n8k16.row.col.f32.f16.f16.f32 "
                 "{%0,%1,%2,%3},{%4,%5,%6,%7},{%8,%9},{%0,%1,%2,%3};"
                 : "+f"(d[0]), "+f"(d[1]), "+f"(d[2]), "+f"(d[3])
                 : "r"(a[0]), "r"(a[1]), "r"(a[2]), "r"(a[3]), "r"(b[0]), "r"(b[1]));
}
__device__ __forceinline__ void cpasync16(unsigned dst, const void* src, int sz) {
    asm volatile("cp.async.cg.shared.global [%0], [%1], 16, %2;\n"
                 :: "r"(dst), "l"(src), "r"(sz));
}
__device__ __forceinline__ void cpcommit() { asm volatile("cp.async.commit_group;\n"); }
__device__ __forceinline__ void cpwait1()  { asm volatile("cp.async.wait_group 1;\n"); }

// ---------------------------------------------------------------------------
// fp32 -> fp16 (rn). which: 0=wg, 1=wu, 2=wd, 3=x
__global__ void convert_h(const float4* __restrict__ src, size_t n4, int which) {
    uint2* d;
    if (which == 0)      d = (uint2*)g_wg;
    else if (which == 1) d = (uint2*)g_wu;
    else if (which == 2) d = (uint2*)g_wd;
    else                 d = (uint2*)g_xf;
    size_t stride = (size_t)gridDim.x * blockDim.x;
    for (size_t i = (size_t)blockIdx.x * blockDim.x + threadIdx.x; i < n4; i += stride) {
        float4 v = src[i];
        __half2 a = __floats2half2_rn(v.x, v.y);
        __half2 b = __floats2half2_rn(v.z, v.w);
        d[i] = make_uint2(*reinterpret_cast<unsigned*>(&a),
                          *reinterpret_cast<unsigned*>(&b));
    }
}

__global__ void zero_kernel(float* __restrict__ out) {
    size_t n = (size_t)T * H;
    size_t stride = (size_t)gridDim.x * blockDim.x;
    for (size_t i = (size_t)blockIdx.x * blockDim.x + threadIdx.x; i < n; i += stride)
        out[i] = 0.f;
    if (blockIdx.x == 0 && threadIdx.x < E) {
        g_cnt[threadIdx.x] = 0;
        g_sumprob[threadIdx.x] = 0.f;
    }
    if (blockIdx.x == 0 && threadIdx.x == E) g_zsum = 0.f;
}

__global__ void router_kernel(const float* __restrict__ x,
                              const float* __restrict__ gw) {
    int warp = threadIdx.x >> 5;
    int lane = threadIdx.x & 31;
    int t = blockIdx.x * (blockDim.x >> 5) + warp;
    if (t >= T) return;

    const float* xr = x + (size_t)t * H;
    float acc[E];
#pragma unroll
    for (int e = 0; e < E; e++) acc[e] = 0.f;
    for (int h = lane; h < H; h += 32) {
        float xv = xr[h];
#pragma unroll
        for (int e = 0; e < E; e++) acc[e] += xv * gw[h * E + e];
    }
#pragma unroll
    for (int off = 16; off; off >>= 1) {
#pragma unroll
        for (int e = 0; e < E; e++)
            acc[e] += __shfl_down_sync(0xffffffffu, acc[e], off);
    }
    if (lane == 0) {
        float m = acc[0];
#pragma unroll
        for (int e = 1; e < E; e++) m = fmaxf(m, acc[e]);
        float p[E], s = 0.f;
#pragma unroll
        for (int e = 0; e < E; e++) { p[e] = __expf(acc[e] - m); s += p[e]; }
        float inv = 1.f / s;
        float lse = m + logf(s);
        atomicAdd(&g_zsum, lse * lse);
        int i1 = 0; float p1 = -1.f;
#pragma unroll
        for (int e = 0; e < E; e++) {
            float pe = p[e] * inv;
            p[e] = pe;
            atomicAdd(&g_sumprob[e], pe);
            if (pe > p1) { p1 = pe; i1 = e; }
        }
        int i2 = -1; float p2 = -1.f;
#pragma unroll
        for (int e = 0; e < E; e++)
            if (e != i1 && p[e] > p2) { p2 = p[e]; i2 = e; }
        float rs = 1.f / (p1 + p2);
        int pos1 = atomicAdd(&g_cnt[i1], 1);
        g_idx[i1][pos1] = t; g_cw[i1][pos1] = p1 * rs;
        int pos2 = atomicAdd(&g_cnt[i2], 1);
        g_idx[i2][pos2] = t; g_cw[i2][pos2] = p2 * rs;
    }
}

// ---------------------------------------------------------------------------
// GEMM1 stage loader: A 128x32 fp16 (gather), B gate/up 32x128 fp16
__device__ __forceinline__ void issue1(int k0, unsigned buf, const int* __restrict__ ridx,
                                       const __half* __restrict__ wg,
                                       const __half* __restrict__ wu,
                                       int col0, int tid) {
#pragma unroll
    for (int i = 0; i < 2; i++) {
        int idx = tid + i * 256; int r = idx >> 2, c = idx & 3;
        int tok = ridx[r];
        int sz = (tok >= 0) ? 16 : 0;
        size_t so = (size_t)(tok >= 0 ? tok : 0) * H + k0 + c * 8;
        cpasync16(buf + r * (APITCH * 2) + c * 16, g_xf + so, sz);
    }
#pragma unroll
    for (int i = 0; i < 2; i++) {
        int idx = tid + i * 256; int r = idx >> 4, c = idx & 15;
        size_t so = (size_t)(k0 + r) * F + col0 + c * 8;
        unsigned db = buf + A_BYTES + r * (BPITCH * 2) + c * 16;
        cpasync16(db,           wg + so, 16);
        cpasync16(db + B_BYTES, wu + so, 16);
    }
}

// GEMM1: CTA 128 x (gate 128 | up 128). 8 warps: 2m x 2n x 2mat, warp tile 64x64.
__global__ __launch_bounds__(NT, 1) void gemm1_tc() {
    int e = blockIdx.z;
    int cnt = g_cnt[e];
    int row0 = blockIdx.x * BM;
    if (row0 >= cnt) return;
    int col0 = blockIdx.y * BN;

    const __half* wg = g_wg + (size_t)e * H * F;
    const __half* wu = g_wu + (size_t)e * H * F;

    extern __shared__ char smem[];
    unsigned sbase = sptr(smem);
    int* ridx = (int*)(smem + NSTAGE * STAGE1);

    int tid = threadIdx.x;
    int lane = tid & 31, wid = tid >> 5;
    int wm2 = (wid & 1) * 64;
    int ng  = wid >> 1;
    int mat = ng >> 1;                  // 0 = gate, 1 = up
    int wn  = (ng & 1) * 64;

    if (tid < BM) { int r = row0 + tid; ridx[tid] = (r < cnt) ? g_idx[e][r] : -1; }
    __syncthreads();

    float acc[4][8][4];
#pragma unroll
    for (int a = 0; a < 4; a++)
#pragma unroll
        for (int b = 0; b < 8; b++)
#pragma unroll
            for (int c = 0; c < 4; c++) acc[a][b][c] = 0.f;

    const int NK = H / BK;   // 32
#pragma unroll
    for (int s = 0; s < NSTAGE - 1; s++) {
        issue1(s * BK, sbase + s * STAGE1, ridx, wg, wu, col0, tid);
        cpcommit();
    }
    cpwait1();
    __syncthreads();

    for (int kt = 0; kt < NK; kt++) {
        int kn = kt + NSTAGE - 1;
        if (kn < NK)
            issue1(kn * BK, sbase + (kn % NSTAGE) * STAGE1, ridx, wg, wu, col0, tid);
        cpcommit();

        unsigned sb = sbase + (kt % NSTAGE) * STAGE1;
        unsigned bbase = sb + A_BYTES + mat * B_BYTES;
#pragma unroll
        for (int ks = 0; ks < 2; ks++) {
            unsigned ah[4][4];
            int ar = wm2 + (lane & 15);
            int ac = ks * 16 + (lane >> 4) * 8;
#pragma unroll
            for (int mi = 0; mi < 4; mi++)
                ldsm4(ah[mi], sb + ((ar + mi * 16) * APITCH + ac) * 2);
            int br = ks * 16 + (lane & 15), bc = wn + (lane >> 4) * 8;
            unsigned bh[4][4];
#pragma unroll
            for (int nh = 0; nh < 4; nh++)
                ldsm4t(bh[nh], bbase + (br * BPITCH + bc + nh * 16) * 2);
#pragma unroll
            for (int mi = 0; mi < 4; mi++)
#pragma unroll
                for (int nh = 0; nh < 4; nh++)
#pragma unroll
                    for (int s = 0; s < 2; s++)
                        mma16816(acc[mi][nh * 2 + s], ah[mi], &bh[nh][s * 2]);
        }
        cpwait1();
        __syncthreads();
    }

    // epilogue: gate warps -> smem; up warps combine silu(g)*u -> g_hf
    __syncthreads();
    float (*sg)[132] = (float(*)[132])smem;   // 128 x 132 floats = 67.6KB
    if (mat == 0) {
#pragma unroll
        for (int mi = 0; mi < 4; mi++)
#pragma unroll
            for (int nj = 0; nj < 8; nj++)
#pragma unroll
                for (int k = 0; k < 4; k++) {
                    int m = wm2 + mi * 16 + (lane >> 2) + (k >> 1) * 8;
                    int n = wn + nj * 8 + (lane & 3) * 2 + (k & 1);
                    sg[m][n] = acc[mi][nj][k];
                }
    }
    __syncthreads();
    if (mat == 1) {
#pragma unroll
        for (int mi = 0; mi < 4; mi++)
#pragma unroll
            for (int half = 0; half < 2; half++) {
                int m = wm2 + mi * 16 + (lane >> 2) + half * 8;
                int r = row0 + m;
                if (r < cnt) {
                    size_t base = ((size_t)e * T + r) * F + col0 + wn + (lane & 3) * 2;
#pragma unroll
                    for (int nj = 0; nj < 8; nj++) {
                        int nl = wn + nj * 8 + (lane & 3) * 2;
                        float g0 = sg[m][nl];
                        float g1 = sg[m][nl + 1];
                        float u0 = acc[mi][nj][half * 2 + 0];
                        float u1 = acc[mi][nj][half * 2 + 1];
                        float h0 = g0 / (1.f + __expf(-g0)) * u0;
                        float h1 = g1 / (1.f + __expf(-g1)) * u1;
                        __half2 hv = __floats2half2_rn(h0, h1);
                        *reinterpret_cast<unsigned*>(g_hf + base + nj * 8) =
                            *reinterpret_cast<unsigned*>(&hv);
                    }
                }
            }
    }
}

// ---------------------------------------------------------------------------
// GEMM2 stage loader: A 128x32 fp16 (linear) + Wd 32x128 fp16
__device__ __forceinline__ void issue2(int k0, unsigned buf, size_t arow0, int rows,
                                       const __half* __restrict__ wd,
                                       int col0, int tid) {
#pragma unroll
    for (int i = 0; i < 2; i++) {
        int idx = tid + i * 256; int r = idx >> 2, c = idx & 3;
        int sz = (r < rows) ? 16 : 0;
        size_t so = (arow0 + (r < rows ? r : 0)) * F + k0 + c * 8;
        cpasync16(buf + r * (APITCH * 2) + c * 16, g_hf + so, sz);
    }
#pragma unroll
    for (int i = 0; i < 2; i++) {
        int idx = tid + i * 256; int r = idx >> 4, c = idx & 15;
        size_t so = (size_t)(k0 + r) * H + col0 + c * 8;
        cpasync16(buf + A_BYTES + r * (BPITCH * 2) + c * 16, wd + so, 16);
    }
}

// GEMM2: CTA 128x128. 8 warps 4m x 2n, warp tile 32x64. Atomic scatter epilogue.
__global__ __launch_bounds__(NT, 1) void gemm2_tc(float* __restrict__ out) {
    int e = blockIdx.z;
    int cnt = g_cnt[e];
    int row0 = blockIdx.x * BM;
    if (row0 >= cnt) return;
    int col0 = blockIdx.y * BN;
    int rows = cnt - row0; if (rows > BM) rows = BM;
    size_t arow0 = (size_t)e * T + row0;

    const __half* wd = g_wd + (size_t)e * F * H;

    extern __shared__ char smem[];
    unsigned sbase = sptr(smem);

    int tid = threadIdx.x;
    int lane = tid & 31, wid = tid >> 5;
    int wm = (wid & 3) * 32, wn = (wid >> 2) * 64;

    float acc[2][8][4];
#pragma unroll
    for (int b = 0; b < 2; b++)
#pragma unroll
        for (int c = 0; c < 8; c++)
#pragma unroll
            for (int d = 0; d < 4; d++) acc[b][c][d] = 0.f;

    const int NK = F / BK;   // 128
#pragma unroll
    for (int s = 0; s < NSTAGE - 1; s++) {
        issue2(s * BK, sbase + s * STAGE2, arow0, rows, wd, col0, tid);
        cpcommit();
    }
    cpwait1();
    __syncthreads();

    for (int kt = 0; kt < NK; kt++) {
        int kn = kt + NSTAGE - 1;
        if (kn < NK)
            issue2(kn * BK, sbase + (kn % NSTAGE) * STAGE2, arow0, rows, wd, col0, tid);
        cpcommit();

        unsigned sb = sbase + (kt % NSTAGE) * STAGE2;
        unsigned bbase = sb + A_BYTES;
#pragma unroll
        for (int ks = 0; ks < 2; ks++) {
            unsigned ah[2][4];
            int ar = wm + (lane & 15);
            int ac = ks * 16 + (lane >> 4) * 8;
#pragma unroll
            for (int mi = 0; mi < 2; mi++)
                ldsm4(ah[mi], sb + ((ar + mi * 16) * APITCH + ac) * 2);
            int br = ks * 16 + (lane & 15), bc = wn + (lane >> 4) * 8;
            unsigned bh[4][4];
#pragma unroll
            for (int nh = 0; nh < 4; nh++)
                ldsm4t(bh[nh], bbase + (br * BPITCH + bc + nh * 16) * 2);
#pragma unroll
            for (int mi = 0; mi < 2; mi++)
#pragma unroll
                for (int nh = 0; nh < 4; nh++)
#pragma unroll
                    for (int s = 0; s < 2; s++)
                        mma16816(acc[mi][nh * 2 + s], ah[mi], &bh[nh][s * 2]);
        }
        cpwait1();
        __syncthreads();
    }

#pragma unroll
    for (int mi = 0; mi < 2; mi++)
#pragma unroll
        for (int half = 0; half < 2; half++) {
            int m = wm + mi * 16 + (lane >> 2) + half * 8;
            int r = row0 + m;
            if (r < cnt) {
                int tok = g_idx[e][r];
                float w = g_cw[e][r];
                float* o = out + (size_t)tok * H + col0 + wn + (lane & 3) * 2;
#pragma unroll
                for (int nj = 0; nj < 8; nj++) {
                    atomicAdd(&o[nj * 8 + 0], w * acc[mi][nj][half * 2 + 0]);
                    atomicAdd(&o[nj * 8 + 1], w * acc[mi][nj][half * 2 + 1]);
                }
            }
        }
}

// ---------------------------------------------------------------------------
__global__ void finalize_kernel(float* __restrict__ out, int out_size) {
    if (threadIdx.x == 0 && blockIdx.x == 0) {
        float bal = 0.f;
#pragma unroll
        for (int e = 0; e < E; e++)
            bal += ((float)g_cnt[e] / (float)(T * TK)) * (g_sumprob[e] / (float)T);
        out[out_size - 2] = (float)E * bal;
        out[out_size - 1] = g_zsum / (float)T;
    }
}

// ---------------------------------------------------------------------------
extern "C" void kernel_launch(void* const* d_in, const int* in_sizes, int n_in,
                              void* d_out, int out_size) {
    const float* x  = (const float*)d_in[0];
    const float* gw = (const float*)d_in[1];
    const float* wg = (const float*)d_in[2];   // [E][H][F]
    const float* wu = (const float*)d_in[3];   // [E][H][F]
    const float* wd = (const float*)d_in[4];   // [E][F][H]
    float* out = (float*)d_out;

    cudaFuncSetAttribute(gemm1_tc, cudaFuncAttributeMaxDynamicSharedMemorySize, SMEM1);
    cudaFuncSetAttribute(gemm2_tc, cudaFuncAttributeMaxDynamicSharedMemorySize, SMEM2);

    zero_kernel<<<512, 256>>>(out);

    size_t nw = (size_t)E * H * F / 4;
    convert_h<<<2048, 256>>>((const float4*)wg, nw, 0);
    convert_h<<<2048, 256>>>((const float4*)wu, nw, 1);
    convert_h<<<2048, 256>>>((const float4*)wd, nw, 2);
    convert_h<<<1024, 256>>>((const float4*)x, (size_t)T * H / 4, 3);

    router_kernel<<<T / 8, 256>>>(x, gw);

    dim3 g1(T / BM, F / BN, E);   // 64 x 32 x 8
    dim3 g2(T / BM, H / BN, E);   // 64 x 8 x 8
    gemm1_tc<<<g1, NT, SMEM1>>>();
    gemm2_tc<<<g2, NT, SMEM2>>>(out);

    finalize_kernel<<<1, 32>>>(out, out_size);
}

// round 16
// speedup vs baseline: 2.1108x; 1.0312x over previous
#include <cuda_runtime.h>
#include <cuda_fp16.h>
#include <stdint.h>
#include <math.h>

#define H 1024
#define F 4096
#define E 8
#define TK 2
#define T 8192

#define BM 128
#define BN1 128           // gemm1 per-matrix N tile
#define BN2 256           // gemm2 N tile
#define BK 32
#define NST1 4
#define NST2 3
#define NT 256

#define APITCH 40          // halves per A row (80 B)
#define B1PITCH 136        // halves per B row, BN1 (272 B)
#define B2PITCH 264        // halves per B row, BN2 (528 B)
#define A_BYTES  (BM * APITCH * 2)       // 10240
#define B1_BYTES (BK * B1PITCH * 2)      // 8704
#define B2_BYTES (BK * B2PITCH * 2)      // 16896
#define STAGE1  (A_BYTES + 2 * B1_BYTES)    // 27648 (A,Bg,Bu)
#define STAGE2  (A_BYTES + B2_BYTES)        // 27136 (A,Bd)
#define SMEM1   (NST1 * STAGE1 + 512)       // 111104
#define SMEM2   (NST2 * STAGE2)             // 81408

// ---- device scratch ----
__device__ int   g_cnt[E];
__device__ int   g_idx[E][T];
__device__ float g_cw[E][T];
__device__ float g_sumprob[E];
__device__ float g_zsum;

// all GEMM operands: single fp16 (rn, unbiased)
__device__ __align__(16) __half g_xf[(size_t)T * H];
__device__ __align__(16) __half g_wg[(size_t)E * H * F];     // [E][H][F] k-major
__device__ __align__(16) __half g_wu[(size_t)E * H * F];
__device__ __align__(16) __half g_wd[(size_t)E * F * H];     // [E][F][H] k-major
// expert e owns rows [e*T, e*T+cnt[e])
__device__ __align__(16) __half g_hf[(size_t)E * T * F];

// ---------------------------------------------------------------------------
__device__ __forceinline__ unsigned sptr(const void* p) {
    return (unsigned)__cvta_generic_to_shared(p);
}
__device__ __forceinline__ void ldsm4(unsigned* r, unsigned a) {
    asm volatile("ldmatrix.sync.aligned.m8n8.x4.shared.b16 {%0,%1,%2,%3}, [%4];"
                 : "=r"(r[0]), "=r"(r[1]), "=r"(r[2]), "=r"(r[3]) : "r"(a));
}
__device__ __forceinline__ void ldsm4t(unsigned* r, unsigned a) {
    asm volatile("ldmatrix.sync.aligned.m8n8.x4.trans.shared.b16 {%0,%1,%2,%3}, [%4];"
                 : "=r"(r[0]), "=r"(r[1]), "=r"(r[2]), "=r"(r[3]) : "r"(a));
}
__device__ __forceinline__ void mma16816(float* d, const unsigned* a, const unsigned* b) {
    asm volatile("mma.sync.aligned.m16n8k16.row.col.f32.f16.f16.f32 "
                 "{%0,%1,%2,%3},{%4,%5,%6,%7},{%8,%9},{%0,%1,%2,%3};"
                 : "+f"(d[0]), "+f"(d[1]), "+f"(d[2]), "+f"(d[3])
                 : "r"(a[0]), "r"(a[1]), "r"(a[2]), "r"(a[3]), "r"(b[0]), "r"(b[1]));
}
__device__ __forceinline__ void cpasync16(unsigned dst, const void* src, int sz) {
    asm volatile("cp.async.cg.shared.global [%0], [%1], 16, %2;\n"
                 :: "r"(dst), "l"(src), "r"(sz));
}
__device__ __forceinline__ void cpcommit() { asm volatile("cp.async.commit_group;\n"); }
__device__ __forceinline__ void cpwait1()  { asm volatile("cp.async.wait_group 1;\n"); }
__device__ __forceinline__ void cpwait2()  { asm volatile("cp.async.wait_group 2;\n"); }

// ---------------------------------------------------------------------------
// all three weight matrices in one launch: blockIdx.y selects the matrix
__global__ void convert_w(const float4* __restrict__ wg, const float4* __restrict__ wu,
                          const float4* __restrict__ wd, size_t n4) {
    const float4* src;
    uint2* d;
    if (blockIdx.y == 0)      { src = wg; d = (uint2*)g_wg; }
    else if (blockIdx.y == 1) { src = wu; d = (uint2*)g_wu; }
    else                      { src = wd; d = (uint2*)g_wd; }
    size_t stride = (size_t)gridDim.x * blockDim.x;
    for (size_t i = (size_t)blockIdx.x * blockDim.x + threadIdx.x; i < n4; i += stride) {
        float4 v = src[i];
        __half2 a = __floats2half2_rn(v.x, v.y);
        __half2 b = __floats2half2_rn(v.z, v.w);
        d[i] = make_uint2(*reinterpret_cast<unsigned*>(&a),
                          *reinterpret_cast<unsigned*>(&b));
    }
}

__global__ void convert_x(const float4* __restrict__ src, size_t n4) {
    uint2* d = (uint2*)g_xf;
    size_t stride = (size_t)gridDim.x * blockDim.x;
    for (size_t i = (size_t)blockIdx.x * blockDim.x + threadIdx.x; i < n4; i += stride) {
        float4 v = src[i];
        __half2 a = __floats2half2_rn(v.x, v.y);
        __half2 b = __floats2half2_rn(v.z, v.w);
        d[i] = make_uint2(*reinterpret_cast<unsigned*>(&a),
                          *reinterpret_cast<unsigned*>(&b));
    }
}

__global__ void zero_kernel(float* __restrict__ out) {
    size_t n = (size_t)T * H;
    size_t stride = (size_t)gridDim.x * blockDim.x;
    for (size_t i = (size_t)blockIdx.x * blockDim.x + threadIdx.x; i < n; i += stride)
        out[i] = 0.f;
    if (blockIdx.x == 0 && threadIdx.x < E) {
        g_cnt[threadIdx.x] = 0;
        g_sumprob[threadIdx.x] = 0.f;
    }
    if (blockIdx.x == 0 && threadIdx.x == E) g_zsum = 0.f;
}

__global__ void router_kernel(const float* __restrict__ x,
                              const float* __restrict__ gw) {
    int warp = threadIdx.x >> 5;
    int lane = threadIdx.x & 31;
    int t = blockIdx.x * (blockDim.x >> 5) + warp;
    if (t >= T) return;

    const float* xr = x + (size_t)t * H;
    float acc[E];
#pragma unroll
    for (int e = 0; e < E; e++) acc[e] = 0.f;
    for (int h = lane; h < H; h += 32) {
        float xv = xr[h];
#pragma unroll
        for (int e = 0; e < E; e++) acc[e] += xv * gw[h * E + e];
    }
#pragma unroll
    for (int off = 16; off; off >>= 1) {
#pragma unroll
        for (int e = 0; e < E; e++)
            acc[e] += __shfl_down_sync(0xffffffffu, acc[e], off);
    }
    if (lane == 0) {
        float m = acc[0];
#pragma unroll
        for (int e = 1; e < E; e++) m = fmaxf(m, acc[e]);
        float p[E], s = 0.f;
#pragma unroll
        for (int e = 0; e < E; e++) { p[e] = __expf(acc[e] - m); s += p[e]; }
        float inv = 1.f / s;
        float lse = m + logf(s);
        atomicAdd(&g_zsum, lse * lse);
        int i1 = 0; float p1 = -1.f;
#pragma unroll
        for (int e = 0; e < E; e++) {
            float pe = p[e] * inv;
            p[e] = pe;
            atomicAdd(&g_sumprob[e], pe);
            if (pe > p1) { p1 = pe; i1 = e; }
        }
        int i2 = -1; float p2 = -1.f;
#pragma unroll
        for (int e = 0; e < E; e++)
            if (e != i1 && p[e] > p2) { p2 = p[e]; i2 = e; }
        float rs = 1.f / (p1 + p2);
        int pos1 = atomicAdd(&g_cnt[i1], 1);
        g_idx[i1][pos1] = t; g_cw[i1][pos1] = p1 * rs;
        int pos2 = atomicAdd(&g_cnt[i2], 1);
        g_idx[i2][pos2] = t; g_cw[i2][pos2] = p2 * rs;
    }
}

// ---------------------------------------------------------------------------
// GEMM1 stage loader: A 128x32 fp16 (gather), B gate/up 32x128 fp16
__device__ __forceinline__ void issue1(int k0, unsigned buf, const int* __restrict__ ridx,
                                       const __half* __restrict__ wg,
                                       const __half* __restrict__ wu,
                                       int col0, int tid) {
#pragma unroll
    for (int i = 0; i < 2; i++) {
        int idx = tid + i * 256; int r = idx >> 2, c = idx & 3;
        int tok = ridx[r];
        int sz = (tok >= 0) ? 16 : 0;
        size_t so = (size_t)(tok >= 0 ? tok : 0) * H + k0 + c * 8;
        cpasync16(buf + r * (APITCH * 2) + c * 16, g_xf + so, sz);
    }
#pragma unroll
    for (int i = 0; i < 2; i++) {
        int idx = tid + i * 256; int r = idx >> 4, c = idx & 15;
        size_t so = (size_t)(k0 + r) * F + col0 + c * 8;
        unsigned db = buf + A_BYTES + r * (B1PITCH * 2) + c * 16;
        cpasync16(db,            wg + so, 16);
        cpasync16(db + B1_BYTES, wu + so, 16);
    }
}

// GEMM1: CTA 128 x (gate 128 | up 128). 8 warps: 2m x 2n x 2mat, warp tile 64x64.
__global__ __launch_bounds__(NT, 1) void gemm1_tc() {
    int e = blockIdx.z;
    int cnt = g_cnt[e];
    int row0 = blockIdx.x * BM;
    if (row0 >= cnt) return;
    int col0 = blockIdx.y * BN1;

    const __half* wg = g_wg + (size_t)e * H * F;
    const __half* wu = g_wu + (size_t)e * H * F;

    extern __shared__ char smem[];
    unsigned sbase = sptr(smem);
    int* ridx = (int*)(smem + NST1 * STAGE1);

    int tid = threadIdx.x;
    int lane = tid & 31, wid = tid >> 5;
    int wm2 = (wid & 1) * 64;
    int ng  = wid >> 1;
    int mat = ng >> 1;                  // 0 = gate, 1 = up
    int wn  = (ng & 1) * 64;

    if (tid < BM) { int r = row0 + tid; ridx[tid] = (r < cnt) ? g_idx[e][r] : -1; }
    __syncthreads();

    float acc[4][8][4];
#pragma unroll
    for (int a = 0; a < 4; a++)
#pragma unroll
        for (int b = 0; b < 8; b++)
#pragma unroll
            for (int c = 0; c < 4; c++) acc[a][b][c] = 0.f;

    const int NK = H / BK;   // 32
#pragma unroll
    for (int s = 0; s < NST1 - 1; s++) {
        issue1(s * BK, sbase + s * STAGE1, ridx, wg, wu, col0, tid);
        cpcommit();
    }
    cpwait2();
    __syncthreads();

    for (int kt = 0; kt < NK; kt++) {
        int kn = kt + NST1 - 1;
        if (kn < NK)
            issue1(kn * BK, sbase + (kn % NST1) * STAGE1, ridx, wg, wu, col0, tid);
        cpcommit();

        unsigned sb = sbase + (kt % NST1) * STAGE1;
        unsigned bbase = sb + A_BYTES + mat * B1_BYTES;
#pragma unroll
        for (int ks = 0; ks < 2; ks++) {
            unsigned ah[4][4];
            int ar = wm2 + (lane & 15);
            int ac = ks * 16 + (lane >> 4) * 8;
#pragma unroll
            for (int mi = 0; mi < 4; mi++)
                ldsm4(ah[mi], sb + ((ar + mi * 16) * APITCH + ac) * 2);
            int br = ks * 16 + (lane & 15), bc = wn + (lane >> 4) * 8;
            unsigned bh[4][4];
#pragma unroll
            for (int nh = 0; nh < 4; nh++)
                ldsm4t(bh[nh], bbase + (br * B1PITCH + bc + nh * 16) * 2);
#pragma unroll
            for (int mi = 0; mi < 4; mi++)
#pragma unroll
                for (int nh = 0; nh < 4; nh++)
#pragma unroll
                    for (int s = 0; s < 2; s++)
                        mma16816(acc[mi][nh * 2 + s], ah[mi], &bh[nh][s * 2]);
        }
        cpwait2();
        __syncthreads();
    }

    // epilogue: gate warps -> smem; up warps combine silu(g)*u -> g_hf
    __syncthreads();
    float (*sg)[132] = (float(*)[132])smem;   // 128 x 132 floats = 67.6KB
    if (mat == 0) {
#pragma unroll
        for (int mi = 0; mi < 4; mi++)
#pragma unroll
            for (int nj = 0; nj < 8; nj++)
#pragma unroll
                for (int k = 0; k < 4; k++) {
                    int m = wm2 + mi * 16 + (lane >> 2) + (k >> 1) * 8;
                    int n = wn + nj * 8 + (lane & 3) * 2 + (k & 1);
                    sg[m][n] = acc[mi][nj][k];
                }
    }
    __syncthreads();
    if (mat == 1) {
#pragma unroll
        for (int mi = 0; mi < 4; mi++)
#pragma unroll
            for (int half = 0; half < 2; half++) {
                int m = wm2 + mi * 16 + (lane >> 2) + half * 8;
                int r = row0 + m;
                if (r < cnt) {
                    size_t base = ((size_t)e * T + r) * F + col0 + wn + (lane & 3) * 2;
#pragma unroll
                    for (int nj = 0; nj < 8; nj++) {
                        int nl = wn + nj * 8 + (lane & 3) * 2;
                        float g0 = sg[m][nl];
                        float g1 = sg[m][nl + 1];
                        float u0 = acc[mi][nj][half * 2 + 0];
                        float u1 = acc[mi][nj][half * 2 + 1];
                        float h0 = g0 / (1.f + __expf(-g0)) * u0;
                        float h1 = g1 / (1.f + __expf(-g1)) * u1;
                        __half2 hv = __floats2half2_rn(h0, h1);
                        *reinterpret_cast<unsigned*>(g_hf + base + nj * 8) =
                            *reinterpret_cast<unsigned*>(&hv);
                    }
                }
            }
    }
}

// ---------------------------------------------------------------------------
// GEMM2 stage loader: A 128x32 fp16 (linear) + Wd 32x256 fp16
__device__ __forceinline__ void issue2(int k0, unsigned buf, size_t arow0, int rows,
                                       const __half* __restrict__ wd,
                                       int col0, int tid) {
#pragma unroll
    for (int i = 0; i < 2; i++) {
        int idx = tid + i * 256; int r = idx >> 2, c = idx & 3;
        int sz = (r < rows) ? 16 : 0;
        size_t so = (arow0 + (r < rows ? r : 0)) * F + k0 + c * 8;
        cpasync16(buf + r * (APITCH * 2) + c * 16, g_hf + so, sz);
    }
#pragma unroll
    for (int i = 0; i < 4; i++) {
        int idx = tid + i * 256; int r = idx >> 5, c = idx & 31;   // 32 rows x 32 chunks
        size_t so = (size_t)(k0 + r) * H + col0 + c * 8;
        cpasync16(buf + A_BYTES + r * (B2PITCH * 2) + c * 16, wd + so, 16);
    }
}

// GEMM2: CTA 128x256. 8 warps 2m x 4n, warp tile 64x64. Atomic scatter epilogue.
__global__ __launch_bounds__(NT, 1) void gemm2_tc(float* __restrict__ out) {
    int e = blockIdx.z;
    int cnt = g_cnt[e];
    int row0 = blockIdx.x * BM;
    if (row0 >= cnt) return;
    int col0 = blockIdx.y * BN2;
    int rows = cnt - row0; if (rows > BM) rows = BM;
    size_t arow0 = (size_t)e * T + row0;

    const __half* wd = g_wd + (size_t)e * F * H;

    extern __shared__ char smem[];
    unsigned sbase = sptr(smem);

    int tid = threadIdx.x;
    int lane = tid & 31, wid = tid >> 5;
    int wm2 = (wid & 1) * 64;
    int wn  = (wid >> 1) * 64;

    float acc[4][8][4];
#pragma unroll
    for (int a = 0; a < 4; a++)
#pragma unroll
        for (int b = 0; b < 8; b++)
#pragma unroll
            for (int c = 0; c < 4; c++) acc[a][b][c] = 0.f;

    const int NK = F / BK;   // 128
#pragma unroll
    for (int s = 0; s < NST2 - 1; s++) {
        issue2(s * BK, sbase + s * STAGE2, arow0, rows, wd, col0, tid);
        cpcommit();
    }
    cpwait1();
    __syncthreads();

    for (int kt = 0; kt < NK; kt++) {
        int kn = kt + NST2 - 1;
        if (kn < NK)
            issue2(kn * BK, sbase + (kn % NST2) * STAGE2, arow0, rows, wd, col0, tid);
        cpcommit();

        unsigned sb = sbase + (kt % NST2) * STAGE2;
        unsigned bbase = sb + A_BYTES;
#pragma unroll
        for (int ks = 0; ks < 2; ks++) {
            unsigned ah[4][4];
            int ar = wm2 + (lane & 15);
            int ac = ks * 16 + (lane >> 4) * 8;
#pragma unroll
            for (int mi = 0; mi < 4; mi++)
                ldsm4(ah[mi], sb + ((ar + mi * 16) * APITCH + ac) * 2);
            int br = ks * 16 + (lane & 15), bc = wn + (lane >> 4) * 8;
            unsigned bh[4][4];
#pragma unroll
            for (int nh = 0; nh < 4; nh++)
                ldsm4t(bh[nh], bbase + (br * B2PITCH + bc + nh * 16) * 2);
#pragma unroll
            for (int mi = 0; mi < 4; mi++)
#pragma unroll
                for (int nh = 0; nh < 4; nh++)
#pragma unroll
                    for (int s = 0; s < 2; s++)
                        mma16816(acc[mi][nh * 2 + s], ah[mi], &bh[nh][s * 2]);
        }
        cpwait1();
        __syncthreads();
    }

#pragma unroll
    for (int mi = 0; mi < 4; mi++)
#pragma unroll
        for (int half = 0; half < 2; half++) {
            int m = wm2 + mi * 16 + (lane >> 2) + half * 8;
            int r = row0 + m;
            if (r < cnt) {
                int tok = g_idx[e][r];
                float w = g_cw[e][r];
                float* o = out + (size_t)tok * H + col0 + wn + (lane & 3) * 2;
#pragma unroll
                for (int nj = 0; nj < 8; nj++) {
                    atomicAdd(&o[nj * 8 + 0], w * acc[mi][nj][half * 2 + 0]);
                    atomicAdd(&o[nj * 8 + 1], w * acc[mi][nj][half * 2 + 1]);
                }
            }
        }
}

// ---------------------------------------------------------------------------
__global__ void finalize_kernel(float* __restrict__ out, int out_size) {
    if (threadIdx.x == 0 && blockIdx.x == 0) {
        float bal = 0.f;
#pragma unroll
        for (int e = 0; e < E; e++)
            bal += ((float)g_cnt[e] / (float)(T * TK)) * (g_sumprob[e] / (float)T);
        out[out_size - 2] = (float)E * bal;
        out[out_size - 1] = g_zsum / (float)T;
    }
}

// ---------------------------------------------------------------------------
extern "C" void kernel_launch(void* const* d_in, const int* in_sizes, int n_in,
                              void* d_out, int out_size) {
    const float* x  = (const float*)d_in[0];
    const float* gw = (const float*)d_in[1];
    const float* wg = (const float*)d_in[2];   // [E][H][F]
    const float* wu = (const float*)d_in[3];   // [E][H][F]
    const float* wd = (const float*)d_in[4];   // [E][F][H]
    float* out = (float*)d_out;

    cudaFuncSetAttribute(gemm1_tc, cudaFuncAttributeMaxDynamicSharedMemorySize, SMEM1);
    cudaFuncSetAttribute(gemm2_tc, cudaFuncAttributeMaxDynamicSharedMemorySize, SMEM2);

    zero_kernel<<<512, 256>>>(out);

    size_t nw = (size_t)E * H * F / 4;
    convert_w<<<dim3(1024, 3), 256>>>((const float4*)wg, (const float4*)wu,
                                      (const float4*)wd, nw);
    convert_x<<<1024, 256>>>((const float4*)x, (size_t)T * H / 4);

    router_kernel<<<T / 8, 256>>>(x, gw);

    dim3 g1(T / BM, F / BN1, E);   // 64 x 32 x 8
    dim3 g2(T / BM, H / BN2, E);   // 64 x 4 x 8
    gemm1_tc<<<g1, NT, SMEM1>>>();
    gemm2_tc<<<g2, NT, SMEM2>>>(out);

    finalize_kernel<<<1, 32>>>(out, out_size);
}

// round 17
// speedup vs baseline: 2.1556x; 1.0212x over previous
#include <cuda_runtime.h>
#include <cuda_fp16.h>
#include <stdint.h>
#include <math.h>

#define H 1024
#define F 4096
#define E 8
#define TK 2
#define T 8192

#define BM 128
#define BN1 128           // gemm1 per-matrix N tile
#define BN2 256           // gemm2 N tile
#define BK 32
#define NST1 4
#define NST2 4
#define NT 256

#define APITCH 40          // halves per A row (80 B)
#define B1PITCH 136        // halves per B row, BN1 (272 B)
#define B2PITCH 264        // halves per B row, BN2 (528 B)
#define A_BYTES  (BM * APITCH * 2)       // 10240
#define B1_BYTES (BK * B1PITCH * 2)      // 8704
#define B2_BYTES (BK * B2PITCH * 2)      // 16896
#define STAGE1  (A_BYTES + 2 * B1_BYTES)    // 27648 (A,Bg,Bu)
#define STAGE2  (A_BYTES + B2_BYTES)        // 27136 (A,Bd)
#define SMEM1   (NST1 * STAGE1 + 512)       // 111104
#define SMEM2   (NST2 * STAGE2)             // 108544

#define RPITCH 1028        // router smem pitch (floats): conflict-free + 16B-aligned

// ---- device scratch ----
__device__ int   g_cnt[E];
__device__ int   g_idx[E][T];
__device__ float g_cw[E][T];
__device__ float g_sumprob[E];
__device__ float g_zsum;

// all GEMM operands: single fp16 (rn, unbiased)
__device__ __align__(16) __half g_xf[(size_t)T * H];
__device__ __align__(16) __half g_wg[(size_t)E * H * F];     // [E][H][F] k-major
__device__ __align__(16) __half g_wu[(size_t)E * H * F];
__device__ __align__(16) __half g_wd[(size_t)E * F * H];     // [E][F][H] k-major
// expert e owns rows [e*T, e*T+cnt[e])
__device__ __align__(16) __half g_hf[(size_t)E * T * F];

// ---------------------------------------------------------------------------
__device__ __forceinline__ unsigned sptr(const void* p) {
    return (unsigned)__cvta_generic_to_shared(p);
}
__device__ __forceinline__ void ldsm4(unsigned* r, unsigned a) {
    asm volatile("ldmatrix.sync.aligned.m8n8.x4.shared.b16 {%0,%1,%2,%3}, [%4];"
                 : "=r"(r[0]), "=r"(r[1]), "=r"(r[2]), "=r"(r[3]) : "r"(a));
}
__device__ __forceinline__ void ldsm4t(unsigned* r, unsigned a) {
    asm volatile("ldmatrix.sync.aligned.m8n8.x4.trans.shared.b16 {%0,%1,%2,%3}, [%4];"
                 : "=r"(r[0]), "=r"(r[1]), "=r"(r[2]), "=r"(r[3]) : "r"(a));
}
__device__ __forceinline__ void mma16816(float* d, const unsigned* a, const unsigned* b) {
    asm volatile("mma.sync.aligned.m16n8k16.row.col.f32.f16.f16.f32 "
                 "{%0,%1,%2,%3},{%4,%5,%6,%7},{%8,%9},{%0,%1,%2,%3};"
                 : "+f"(d[0]), "+f"(d[1]), "+f"(d[2]), "+f"(d[3])
                 : "r"(a[0]), "r"(a[1]), "r"(a[2]), "r"(a[3]), "r"(b[0]), "r"(b[1]));
}
__device__ __forceinline__ void cpasync16(unsigned dst, const void* src, int sz) {
    asm volatile("cp.async.cg.shared.global [%0], [%1], 16, %2;\n"
                 :: "r"(dst), "l"(src), "r"(sz));
}
__device__ __forceinline__ void cpcommit() { asm volatile("cp.async.commit_group;\n"); }
__device__ __forceinline__ void cpwait2()  { asm volatile("cp.async.wait_group 2;\n"); }

// ---------------------------------------------------------------------------
// all three weight matrices in one launch: blockIdx.y selects the matrix
__global__ void convert_w(const float4* __restrict__ wg, const float4* __restrict__ wu,
                          const float4* __restrict__ wd, size_t n4) {
    const float4* src;
    uint2* d;
    if (blockIdx.y == 0)      { src = wg; d = (uint2*)g_wg; }
    else if (blockIdx.y == 1) { src = wu; d = (uint2*)g_wu; }
    else                      { src = wd; d = (uint2*)g_wd; }
    size_t stride = (size_t)gridDim.x * blockDim.x;
    for (size_t i = (size_t)blockIdx.x * blockDim.x + threadIdx.x; i < n4; i += stride) {
        float4 v = src[i];
        __half2 a = __floats2half2_rn(v.x, v.y);
        __half2 b = __floats2half2_rn(v.z, v.w);
        d[i] = make_uint2(*reinterpret_cast<unsigned*>(&a),
                          *reinterpret_cast<unsigned*>(&b));
    }
}

__global__ void zero_kernel(float* __restrict__ out) {
    size_t n = (size_t)T * H;
    size_t stride = (size_t)gridDim.x * blockDim.x;
    for (size_t i = (size_t)blockIdx.x * blockDim.x + threadIdx.x; i < n; i += stride)
        out[i] = 0.f;
    if (blockIdx.x == 0 && threadIdx.x < E) {
        g_cnt[threadIdx.x] = 0;
        g_sumprob[threadIdx.x] = 0.f;
    }
    if (blockIdx.x == 0 && threadIdx.x == E) g_zsum = 0.f;
}

// ---------------------------------------------------------------------------
// Router v2: smem-staged transposed gw, float4 x loads, fused fp16 convert of x.
__global__ void router_kernel(const float4* __restrict__ x4,
                              const float* __restrict__ gw) {
    __shared__ float gwT[E * RPITCH];    // 32.9 KB
    int tid = threadIdx.x;
    for (int i = tid; i < H * E; i += 256) {
        int h = i >> 3, e = i & 7;
        gwT[e * RPITCH + h] = gw[i];
    }
    __syncthreads();

    int warp = tid >> 5, lane = tid & 31;
    int t = blockIdx.x * 8 + warp;
    const float4* xr = x4 + (size_t)t * (H / 4);
    uint2* xo = (uint2*)(g_xf + (size_t)t * H);

    float acc[E];
#pragma unroll
    for (int e = 0; e < E; e++) acc[e] = 0.f;

#pragma unroll
    for (int i = 0; i < H / 128; i++) {          // 8 iters
        int idx = i * 32 + lane;                  // float4 index within row
        float4 v = xr[idx];
        __half2 a = __floats2half2_rn(v.x, v.y);
        __half2 b = __floats2half2_rn(v.z, v.w);
        xo[idx] = make_uint2(*reinterpret_cast<unsigned*>(&a),
                             *reinterpret_cast<unsigned*>(&b));
#pragma unroll
        for (int e = 0; e < E; e++) {
            float4 g = *reinterpret_cast<const float4*>(&gwT[e * RPITCH + idx * 4]);
            acc[e] += v.x * g.x + v.y * g.y + v.z * g.z + v.w * g.w;
        }
    }
#pragma unroll
    for (int off = 16; off; off >>= 1) {
#pragma unroll
        for (int e = 0; e < E; e++)
            acc[e] += __shfl_down_sync(0xffffffffu, acc[e], off);
    }

    if (lane == 0) {
        float m = acc[0];
#pragma unroll
        for (int e = 1; e < E; e++) m = fmaxf(m, acc[e]);
        float p[E], s = 0.f;
#pragma unroll
        for (int e = 0; e < E; e++) { p[e] = __expf(acc[e] - m); s += p[e]; }
        float inv = 1.f / s;
        float lse = m + logf(s);
        atomicAdd(&g_zsum, lse * lse);
        int i1 = 0; float p1 = -1.f;
#pragma unroll
        for (int e = 0; e < E; e++) {
            float pe = p[e] * inv;
            p[e] = pe;
            atomicAdd(&g_sumprob[e], pe);
            if (pe > p1) { p1 = pe; i1 = e; }
        }
        int i2 = -1; float p2 = -1.f;
#pragma unroll
        for (int e = 0; e < E; e++)
            if (e != i1 && p[e] > p2) { p2 = p[e]; i2 = e; }
        float rs = 1.f / (p1 + p2);
        int pos1 = atomicAdd(&g_cnt[i1], 1);
        g_idx[i1][pos1] = t; g_cw[i1][pos1] = p1 * rs;
        int pos2 = atomicAdd(&g_cnt[i2], 1);
        g_idx[i2][pos2] = t; g_cw[i2][pos2] = p2 * rs;
    }
}

// ---------------------------------------------------------------------------
// GEMM1 stage loader: A 128x32 fp16 (gather), B gate/up 32x128 fp16
__device__ __forceinline__ void issue1(int k0, unsigned buf, const int* __restrict__ ridx,
                                       const __half* __restrict__ wg,
                                       const __half* __restrict__ wu,
                                       int col0, int tid) {
#pragma unroll
    for (int i = 0; i < 2; i++) {
        int idx = tid + i * 256; int r = idx >> 2, c = idx & 3;
        int tok = ridx[r];
        int sz = (tok >= 0) ? 16 : 0;
        size_t so = (size_t)(tok >= 0 ? tok : 0) * H + k0 + c * 8;
        cpasync16(buf + r * (APITCH * 2) + c * 16, g_xf + so, sz);
    }
#pragma unroll
    for (int i = 0; i < 2; i++) {
        int idx = tid + i * 256; int r = idx >> 4, c = idx & 15;
        size_t so = (size_t)(k0 + r) * F + col0 + c * 8;
        unsigned db = buf + A_BYTES + r * (B1PITCH * 2) + c * 16;
        cpasync16(db,            wg + so, 16);
        cpasync16(db + B1_BYTES, wu + so, 16);
    }
}

// GEMM1: CTA 128 x (gate 128 | up 128). 8 warps: 2m x 2n x 2mat, warp tile 64x64.
__global__ __launch_bounds__(NT, 1) void gemm1_tc() {
    int e = blockIdx.z;
    int cnt = g_cnt[e];
    int row0 = blockIdx.x * BM;
    if (row0 >= cnt) return;
    int col0 = blockIdx.y * BN1;

    const __half* wg = g_wg + (size_t)e * H * F;
    const __half* wu = g_wu + (size_t)e * H * F;

    extern __shared__ char smem[];
    unsigned sbase = sptr(smem);
    int* ridx = (int*)(smem + NST1 * STAGE1);

    int tid = threadIdx.x;
    int lane = tid & 31, wid = tid >> 5;
    int wm2 = (wid & 1) * 64;
    int ng  = wid >> 1;
    int mat = ng >> 1;                  // 0 = gate, 1 = up
    int wn  = (ng & 1) * 64;

    if (tid < BM) { int r = row0 + tid; ridx[tid] = (r < cnt) ? g_idx[e][r] : -1; }
    __syncthreads();

    float acc[4][8][4];
#pragma unroll
    for (int a = 0; a < 4; a++)
#pragma unroll
        for (int b = 0; b < 8; b++)
#pragma unroll
            for (int c = 0; c < 4; c++) acc[a][b][c] = 0.f;

    const int NK = H / BK;   // 32
#pragma unroll
    for (int s = 0; s < NST1 - 1; s++) {
        issue1(s * BK, sbase + s * STAGE1, ridx, wg, wu, col0, tid);
        cpcommit();
    }
    cpwait2();
    __syncthreads();

    for (int kt = 0; kt < NK; kt++) {
        int kn = kt + NST1 - 1;
        if (kn < NK)
            issue1(kn * BK, sbase + (kn % NST1) * STAGE1, ridx, wg, wu, col0, tid);
        cpcommit();

        unsigned sb = sbase + (kt % NST1) * STAGE1;
        unsigned bbase = sb + A_BYTES + mat * B1_BYTES;
#pragma unroll
        for (int ks = 0; ks < 2; ks++) {
            unsigned ah[4][4];
            int ar = wm2 + (lane & 15);
            int ac = ks * 16 + (lane >> 4) * 8;
#pragma unroll
            for (int mi = 0; mi < 4; mi++)
                ldsm4(ah[mi], sb + ((ar + mi * 16) * APITCH + ac) * 2);
            int br = ks * 16 + (lane & 15), bc = wn + (lane >> 4) * 8;
            unsigned bh[4][4];
#pragma unroll
            for (int nh = 0; nh < 4; nh++)
                ldsm4t(bh[nh], bbase + (br * B1PITCH + bc + nh * 16) * 2);
#pragma unroll
            for (int mi = 0; mi < 4; mi++)
#pragma unroll
                for (int nh = 0; nh < 4; nh++)
#pragma unroll
                    for (int s = 0; s < 2; s++)
                        mma16816(acc[mi][nh * 2 + s], ah[mi], &bh[nh][s * 2]);
        }
        cpwait2();
        __syncthreads();
    }

    // epilogue: gate warps -> smem; up warps combine silu(g)*u -> g_hf
    __syncthreads();
    float (*sg)[132] = (float(*)[132])smem;   // 128 x 132 floats = 67.6KB
    if (mat == 0) {
#pragma unroll
        for (int mi = 0; mi < 4; mi++)
#pragma unroll
            for (int nj = 0; nj < 8; nj++)
#pragma unroll
                for (int k = 0; k < 4; k++) {
                    int m = wm2 + mi * 16 + (lane >> 2) + (k >> 1) * 8;
                    int n = wn + nj * 8 + (lane & 3) * 2 + (k & 1);
                    sg[m][n] = acc[mi][nj][k];
                }
    }
    __syncthreads();
    if (mat == 1) {
#pragma unroll
        for (int mi = 0; mi < 4; mi++)
#pragma unroll
            for (int half = 0; half < 2; half++) {
                int m = wm2 + mi * 16 + (lane >> 2) + half * 8;
                int r = row0 + m;
                if (r < cnt) {
                    size_t base = ((size_t)e * T + r) * F + col0 + wn + (lane & 3) * 2;
#pragma unroll
                    for (int nj = 0; nj < 8; nj++) {
                        int nl = wn + nj * 8 + (lane & 3) * 2;
                        float g0 = sg[m][nl];
                        float g1 = sg[m][nl + 1];
                        float u0 = acc[mi][nj][half * 2 + 0];
                        float u1 = acc[mi][nj][half * 2 + 1];
                        float h0 = g0 / (1.f + __expf(-g0)) * u0;
                        float h1 = g1 / (1.f + __expf(-g1)) * u1;
                        __half2 hv = __floats2half2_rn(h0, h1);
                        *reinterpret_cast<unsigned*>(g_hf + base + nj * 8) =
                            *reinterpret_cast<unsigned*>(&hv);
                    }
                }
            }
    }
}

// ---------------------------------------------------------------------------
// GEMM2 stage loader: A 128x32 fp16 (linear) + Wd 32x256 fp16
__device__ __forceinline__ void issue2(int k0, unsigned buf, size_t arow0, int rows,
                                       const __half* __restrict__ wd,
                                       int col0, int tid) {
#pragma unroll
    for (int i = 0; i < 2; i++) {
        int idx = tid + i * 256; int r = idx >> 2, c = idx & 3;
        int sz = (r < rows) ? 16 : 0;
        size_t so = (arow0 + (r < rows ? r : 0)) * F + k0 + c * 8;
        cpasync16(buf + r * (APITCH * 2) + c * 16, g_hf + so, sz);
    }
#pragma unroll
    for (int i = 0; i < 4; i++) {
        int idx = tid + i * 256; int r = idx >> 5, c = idx & 31;   // 32 rows x 32 chunks
        size_t so = (size_t)(k0 + r) * H + col0 + c * 8;
        cpasync16(buf + A_BYTES + r * (B2PITCH * 2) + c * 16, wd + so, 16);
    }
}

// GEMM2: CTA 128x256. 8 warps 2m x 4n, warp tile 64x64. Atomic scatter epilogue.
__global__ __launch_bounds__(NT, 1) void gemm2_tc(float* __restrict__ out) {
    int e = blockIdx.z;
    int cnt = g_cnt[e];
    int row0 = blockIdx.x * BM;
    if (row0 >= cnt) return;
    int col0 = blockIdx.y * BN2;
    int rows = cnt - row0; if (rows > BM) rows = BM;
    size_t arow0 = (size_t)e * T + row0;

    const __half* wd = g_wd + (size_t)e * F * H;

    extern __shared__ char smem[];
    unsigned sbase = sptr(smem);

    int tid = threadIdx.x;
    int lane = tid & 31, wid = tid >> 5;
    int wm2 = (wid & 1) * 64;
    int wn  = (wid >> 1) * 64;

    float acc[4][8][4];
#pragma unroll
    for (int a = 0; a < 4; a++)
#pragma unroll
        for (int b = 0; b < 8; b++)
#pragma unroll
            for (int c = 0; c < 4; c++) acc[a][b][c] = 0.f;

    const int NK = F / BK;   // 128
#pragma unroll
    for (int s = 0; s < NST2 - 1; s++) {
        issue2(s * BK, sbase + s * STAGE2, arow0, rows, wd, col0, tid);
        cpcommit();
    }
    cpwait2();
    __syncthreads();

    for (int kt = 0; kt < NK; kt++) {
        int kn = kt + NST2 - 1;
        if (kn < NK)
            issue2(kn * BK, sbase + (kn % NST2) * STAGE2, arow0, rows, wd, col0, tid);
        cpcommit();

        unsigned sb = sbase + (kt % NST2) * STAGE2;
        unsigned bbase = sb + A_BYTES;
#pragma unroll
        for (int ks = 0; ks < 2; ks++) {
            unsigned ah[4][4];
            int ar = wm2 + (lane & 15);
            int ac = ks * 16 + (lane >> 4) * 8;
#pragma unroll
            for (int mi = 0; mi < 4; mi++)
                ldsm4(ah[mi], sb + ((ar + mi * 16) * APITCH + ac) * 2);
            int br = ks * 16 + (lane & 15), bc = wn + (lane >> 4) * 8;
            unsigned bh[4][4];
#pragma unroll
            for (int nh = 0; nh < 4; nh++)
                ldsm4t(bh[nh], bbase + (br * B2PITCH + bc + nh * 16) * 2);
#pragma unroll
            for (int mi = 0; mi < 4; mi++)
#pragma unroll
                for (int nh = 0; nh < 4; nh++)
#pragma unroll
                    for (int s = 0; s < 2; s++)
                        mma16816(acc[mi][nh * 2 + s], ah[mi], &bh[nh][s * 2]);
        }
        cpwait2();
        __syncthreads();
    }

#pragma unroll
    for (int mi = 0; mi < 4; mi++)
#pragma unroll
        for (int half = 0; half < 2; half++) {
            int m = wm2 + mi * 16 + (lane >> 2) + half * 8;
            int r = row0 + m;
            if (r < cnt) {
                int tok = g_idx[e][r];
                float w = g_cw[e][r];
                float* o = out + (size_t)tok * H + col0 + wn + (lane & 3) * 2;
#pragma unroll
                for (int nj = 0; nj < 8; nj++) {
                    atomicAdd(&o[nj * 8 + 0], w * acc[mi][nj][half * 2 + 0]);
                    atomicAdd(&o[nj * 8 + 1], w * acc[mi][nj][half * 2 + 1]);
                }
            }
        }
}

// ---------------------------------------------------------------------------
__global__ void finalize_kernel(float* __restrict__ out, int out_size) {
    if (threadIdx.x == 0 && blockIdx.x == 0) {
        float bal = 0.f;
#pragma unroll
        for (int e = 0; e < E; e++)
            bal += ((float)g_cnt[e] / (float)(T * TK)) * (g_sumprob[e] / (float)T);
        out[out_size - 2] = (float)E * bal;
        out[out_size - 1] = g_zsum / (float)T;
    }
}

// ---------------------------------------------------------------------------
extern "C" void kernel_launch(void* const* d_in, const int* in_sizes, int n_in,
                              void* d_out, int out_size) {
    const float* x  = (const float*)d_in[0];
    const float* gw = (const float*)d_in[1];
    const float* wg = (const float*)d_in[2];   // [E][H][F]
    const float* wu = (const float*)d_in[3];   // [E][H][F]
    const float* wd = (const float*)d_in[4];   // [E][F][H]
    float* out = (float*)d_out;

    cudaFuncSetAttribute(gemm1_tc, cudaFuncAttributeMaxDynamicSharedMemorySize, SMEM1);
    cudaFuncSetAttribute(gemm2_tc, cudaFuncAttributeMaxDynamicSharedMemorySize, SMEM2);

    zero_kernel<<<512, 256>>>(out);

    size_t nw = (size_t)E * H * F / 4;
    convert_w<<<dim3(1024, 3), 256>>>((const float4*)wg, (const float4*)wu,
                                      (const float4*)wd, nw);

    router_kernel<<<T / 8, 256>>>((const float4*)x, gw);   // also converts x -> g_xf

    dim3 g1(T / BM, F / BN1, E);   // 64 x 32 x 8
    dim3 g2(T / BM, H / BN2, E);   // 64 x 4 x 8
    gemm1_tc<<<g1, NT, SMEM1>>>();
    gemm2_tc<<<g2, NT, SMEM2>>>(out);

    finalize_kernel<<<1, 32>>>(out, out_size);
}